// round 13
// baseline (speedup 1.0000x reference)
#include <cuda_runtime.h>
#include <cuda_bf16.h>
#include <math.h>
#include <stdint.h>

#define BATCH 4
#define SEQ   2048
#define DIM   1024
#define MROWS (BATCH*SEQ)   // 8192

// ---------------------------------------------------------------------------
// Scratch (__device__ globals; runtime allocation is forbidden)
// ---------------------------------------------------------------------------
__device__ __nv_bfloat16 g_xhi[MROWS*DIM],  g_xlo[MROWS*DIM];
__device__ __nv_bfloat16 g_Whi[4*DIM*DIM],  g_Wlo[4*DIM*DIM];   // stacked Q,K,V,O
__device__ __nv_bfloat16 g_Qhi[MROWS*DIM],  g_Qlo[MROWS*DIM];
__device__ __nv_bfloat16 g_Khi[MROWS*DIM],  g_Klo[MROWS*DIM];
__device__ __nv_bfloat16 g_Vthi[MROWS*DIM], g_Vtlo[MROWS*DIM];  // [B, D, S]
__device__ float         g_Pf[(size_t)BATCH*SEQ*SEQ];
__device__ __nv_bfloat16 g_Phi[(size_t)BATCH*SEQ*SEQ], g_Plo[(size_t)BATCH*SEQ*SEQ];
__device__ __nv_bfloat16 g_Ohi[MROWS*DIM],  g_Olo[MROWS*DIM];

// ---------------------------------------------------------------------------
// Helpers
// ---------------------------------------------------------------------------
__device__ __forceinline__ uint32_t smem_u32(const void* p) {
    uint32_t a;
    asm("{ .reg .u64 t; cvta.to.shared.u64 t, %1; cvt.u32.u64 %0, t; }" : "=r"(a) : "l"(p));
    return a;
}

// XOR swizzle for 64B-row tiles (8 rows x 64B atom): conflict-free ldmatrix
#define SWZ64(off) ((uint32_t)(off) ^ (((uint32_t)(off) >> 3) & 0x30))

#define CP16(dst, src) \
    asm volatile("cp.async.cg.shared.global [%0], [%1], 16;" :: "r"(dst), "l"(src))
#define CPCOMMIT() asm volatile("cp.async.commit_group;" ::: "memory")
#define CPWAIT(n)  asm volatile("cp.async.wait_group %0;" :: "n"(n) : "memory")

__device__ __forceinline__ void ldm4(uint32_t* r, uint32_t addr) {
    asm volatile("ldmatrix.sync.aligned.m8n8.x4.shared.b16 {%0,%1,%2,%3}, [%4];"
        : "=r"(r[0]), "=r"(r[1]), "=r"(r[2]), "=r"(r[3]) : "r"(addr));
}

__device__ __forceinline__ void mma16816(float* c, const uint32_t* a, const uint32_t* b) {
    asm volatile("mma.sync.aligned.m16n8k16.row.col.f32.bf16.bf16.f32 "
        "{%0,%1,%2,%3}, {%4,%5,%6,%7}, {%8,%9}, {%0,%1,%2,%3};"
        : "+f"(c[0]), "+f"(c[1]), "+f"(c[2]), "+f"(c[3])
        : "r"(a[0]), "r"(a[1]), "r"(a[2]), "r"(a[3]), "r"(b[0]), "r"(b[1]));
}

// pack two fp32 into bf16x2 + residual bf16x2
__device__ __forceinline__ void split2(float v0, float v1,
                                       __nv_bfloat162& hi2, __nv_bfloat162& lo2) {
    __nv_bfloat16 h0 = __float2bfloat16(v0), h1 = __float2bfloat16(v1);
    hi2 = __nv_bfloat162(h0, h1);
    lo2 = __nv_bfloat162(__float2bfloat16(v0 - __bfloat162float(h0)),
                         __float2bfloat16(v1 - __bfloat162float(h1)));
}

// ---------------------------------------------------------------------------
// Tensor-core GEMM: C(128x128 tiles) = A * B^T, 3-MMA bf16 split precision.
// NTN = n-tiles (8 cols each) per warp:
//   NTN=4: 256 thr, 8 warps 2x4, warp 64x32
//   NTN=8: 128 thr, 4 warps 2x2, warp 64x64  (min smem traffic per MAC)
// 2 CTAs/SM in both configs.
// EPI: 0 = fp32 out (+bias), 1 = bf16 hi/lo out, 3 = QKV-routed (Q/K direct,
//      V transposed via smem staging). hi/lo stores are packed bf16x2.
// CAUSAL: exact triangular grid decode, longest-first
// ---------------------------------------------------------------------------
#define STAGE_BYTES 32768
#define OFF_AHI 0
#define OFF_ALO 8192
#define OFF_BHI 16384
#define OFF_BLO 24576
#define SMEM_BYTES 65536     // 2 stages
#define TPITCH 136           // transpose staging pitch (bf16 elements)

template<int EPI, bool CAUSAL, bool KBOUND, bool HASBIAS, bool REV, int NTN>
__global__ void __launch_bounds__((NTN==4 ? 256 : 128), 2)
k_tc(const __nv_bfloat16* __restrict__ Ahi, const __nv_bfloat16* __restrict__ Alo,
     const __nv_bfloat16* __restrict__ Bhi, const __nv_bfloat16* __restrict__ Blo,
     float* __restrict__ Cf, __nv_bfloat16* __restrict__ Chi, __nv_bfloat16* __restrict__ Clo,
     const float* __restrict__ bias,
     int N, int Kdim, long long sA, long long sB, long long sC)
{
    constexpr int NT = (NTN==4 ? 256 : 128);   // threads
    constexpr int WNOFF = NTN * 8;             // warp n-span
    int m0, n0;
    if (CAUSAL) {
        // longest-first: reverse the triangular index
        const int tix = (int)gridDim.x - 1 - (int)blockIdx.x;
        int mb = (int)((sqrtf(8.f * tix + 1.f) - 1.f) * 0.5f + 1e-4f);
        while ((mb + 1) * (mb + 2) / 2 <= tix) ++mb;
        while (mb * (mb + 1) / 2 > tix) --mb;
        const int nb = tix - mb * (mb + 1) / 2;
        m0 = mb * 128;
        n0 = nb * 128;
    } else {
        const int by = REV ? (gridDim.y - 1 - blockIdx.y) : blockIdx.y;
        m0 = by * 128;
        n0 = blockIdx.x * 128;
    }
    const long long b = blockIdx.z;
    Ahi += b * sA; Alo += b * sA;
    Bhi += b * sB; Blo += b * sB;

    extern __shared__ char smem[];
    const uint32_t sb = smem_u32(smem);
    const int tid = threadIdx.x, lane = tid & 31, wid = tid >> 5;
    const int wm = wid & 1, wn = wid >> 1;     // warp tile 64(m) x WNOFF(n)

    const int kend = KBOUND ? (m0 + 128) : Kdim;
    const int nchunk = kend >> 5;              // BK = 32

    float acc[4][NTN][4];
    #pragma unroll
    for (int i = 0; i < 4; ++i)
        #pragma unroll
        for (int j = 0; j < NTN; ++j)
            #pragma unroll
            for (int r = 0; r < 4; ++r) acc[i][j][r] = 0.f;

    // stage loader: 4 tiles of 128 rows x 64B, SWZ64 layout, cp.async 16B
    auto load_stage = [&](int c, int s) {
        const int k0 = c << 5;
        const uint32_t sbase = sb + s * STAGE_BYTES;
        #pragma unroll
        for (int h = 0; h < 512/NT; ++h) {
            const int idx = tid + h * NT;      // 0..511
            const int row = idx >> 2, ch = idx & 3;
            const uint32_t so = SWZ64(row * 64 + ch * 16);
            const size_t gA = (size_t)(m0 + row) * Kdim + k0 + ch * 8;
            const size_t gB = (size_t)(n0 + row) * Kdim + k0 + ch * 8;
            CP16(sbase + OFF_AHI + so, Ahi + gA);
            CP16(sbase + OFF_ALO + so, Alo + gA);
            CP16(sbase + OFF_BHI + so, Bhi + gB);
            CP16(sbase + OFF_BLO + so, Blo + gB);
        }
    };

    load_stage(0, 0); CPCOMMIT();

    // Single-barrier pipeline: wait(c) -> barrier -> issue(c+1) -> consume(c).
    for (int c = 0; c < nchunk; ++c) {
        CPWAIT(0);
        __syncthreads();
        if (c + 1 < nchunk) { load_stage(c + 1, (c + 1) & 1); CPCOMMIT(); }

        const uint32_t sA = sb + (c & 1) * STAGE_BYTES;
        #pragma unroll
        for (int kk = 0; kk < 32; kk += 16) {
            // B fragments: NTN nt tiles (hi+lo)
            uint32_t bhi[NTN][2], blo[NTN][2];
            const int brow  = (lane & 7) + ((lane & 16) ? 8 : 0);
            const int bkoff = (lane & 8) ? 8 : 0;
            #pragma unroll
            for (int np = 0; np < NTN/2; ++np) {
                const uint32_t off = SWZ64((wn*WNOFF + np*16 + brow) * 64 + (kk + bkoff) * 2);
                uint32_t t4[4];
                ldm4(t4, sA + OFF_BHI + off);
                bhi[np*2][0] = t4[0]; bhi[np*2][1] = t4[1];
                bhi[np*2+1][0] = t4[2]; bhi[np*2+1][1] = t4[3];
                ldm4(t4, sA + OFF_BLO + off);
                blo[np*2][0] = t4[0]; blo[np*2][1] = t4[1];
                blo[np*2+1][0] = t4[2]; blo[np*2+1][1] = t4[3];
            }
            // A fragments: 4 mt tiles, hi and lo in separate regs
            const int arow  = lane & 15;
            const int akoff = (lane >> 4) << 3;
            uint32_t ahi[4][4], alo[4][4];
            #pragma unroll
            for (int mt = 0; mt < 4; ++mt) {
                const uint32_t off = SWZ64((wm*64 + mt*16 + arow) * 64 + (kk + akoff) * 2);
                ldm4(ahi[mt], sA + OFF_AHI + off);
                ldm4(alo[mt], sA + OFF_ALO + off);
            }
            // pass 1: hi*hi
            #pragma unroll
            for (int mt = 0; mt < 4; ++mt)
                #pragma unroll
                for (int nt = 0; nt < NTN; ++nt)
                    mma16816(acc[mt][nt], ahi[mt], bhi[nt]);
            // pass 2: hi*lo
            #pragma unroll
            for (int mt = 0; mt < 4; ++mt)
                #pragma unroll
                for (int nt = 0; nt < NTN; ++nt)
                    mma16816(acc[mt][nt], ahi[mt], blo[nt]);
            // pass 3: lo*hi
            #pragma unroll
            for (int mt = 0; mt < 4; ++mt)
                #pragma unroll
                for (int nt = 0; nt < NTN; ++nt)
                    mma16816(acc[mt][nt], alo[mt], bhi[nt]);
        }
    }

    // Epilogue. C frag: (c0,c1) row g cols t*2,t*2+1; (c2,c3) row g+8.
    const int g = lane >> 2, t = lane & 3;
    const bool vpath = (EPI == 3) && (n0 >= 2*DIM);
    if (vpath) {
        // V projection: smem-staged transpose [n][m], coalesced stores along s.
        __syncthreads();   // laggards may still be reading stage smem
        __nv_bfloat16* tsm = (__nv_bfloat16*)smem;
        const int bb = m0 >> 11, sbase_s = m0 & 2047;
        const int nvl0 = n0 - 2*DIM;
        #pragma unroll
        for (int comp = 0; comp < 2; ++comp) {
            #pragma unroll
            for (int mt = 0; mt < 4; ++mt)
                #pragma unroll
                for (int nt = 0; nt < NTN; ++nt)
                    #pragma unroll
                    for (int h = 0; h < 2; ++h) {
                        const int ml = wm*64 + mt*16 + g + h*8;
                        const int nl = wn*WNOFF + nt*8 + t*2;
                        float v0 = acc[mt][nt][h*2], v1 = acc[mt][nt][h*2+1];
                        __nv_bfloat162 hi2, lo2;
                        split2(v0, v1, hi2, lo2);
                        __nv_bfloat162 o2 = (comp == 0) ? hi2 : lo2;
                        tsm[(size_t)nl * TPITCH + ml]     = o2.x;
                        tsm[(size_t)(nl+1) * TPITCH + ml] = o2.y;
                    }
            __syncthreads();
            __nv_bfloat16* dst = (comp == 0) ? g_Vthi : g_Vtlo;
            // NT threads cover 128 rows x (NT/128) col-chunks
            constexpr int CHW = 16384 / NT;    // bf16 per thread (64 or 128)
            const int nl = tid / (NT/128), mh = (tid % (NT/128)) * CHW;
            const __nv_bfloat16* srow = tsm + (size_t)nl * TPITCH + mh;
            __nv_bfloat16* drow = dst + ((size_t)bb * DIM + (nvl0 + nl)) * SEQ + sbase_s + mh;
            #pragma unroll
            for (int q = 0; q < CHW/8; ++q)
                *(uint4*)(drow + q*8) = *(const uint4*)(srow + q*8);
            __syncthreads();
        }
        return;
    }
    #pragma unroll
    for (int mt = 0; mt < 4; ++mt)
        #pragma unroll
        for (int nt = 0; nt < NTN; ++nt)
            #pragma unroll
            for (int h = 0; h < 2; ++h) {
                const int m  = m0 + wm*64 + mt*16 + g + h*8;
                const int nb = n0 + wn*WNOFF + nt*8 + t*2;
                float v0 = acc[mt][nt][h*2], v1 = acc[mt][nt][h*2+1];
                if (EPI == 0) {
                    if (HASBIAS) { v0 += bias[nb]; v1 += bias[nb+1]; }
                    float* o = Cf + b*sC + (size_t)m*N + nb;
                    o[0] = v0; o[1] = v1;
                } else if (EPI == 1) {
                    const size_t base = (size_t)(b*sC) + (size_t)m*N + nb;
                    __nv_bfloat162 hi2, lo2;
                    split2(v0, v1, hi2, lo2);
                    *(__nv_bfloat162*)(Chi + base) = hi2;
                    *(__nv_bfloat162*)(Clo + base) = lo2;
                } else {  // EPI==3, Q/K route
                    const int which = nb >> 10;         // 0=Q, 1=K
                    const int nl = nb & 1023;
                    __nv_bfloat16* dh = which ? g_Khi : g_Qhi;
                    __nv_bfloat16* dl = which ? g_Klo : g_Qlo;
                    const size_t base = (size_t)m * DIM + nl;
                    __nv_bfloat162 hi2, lo2;
                    split2(v0, v1, hi2, lo2);
                    *(__nv_bfloat162*)(dh + base) = hi2;
                    *(__nv_bfloat162*)(dl + base) = lo2;
                }
            }
}

// ---------------------------------------------------------------------------
// fp32 -> (bf16 hi, bf16 lo) split, grid-strided, 4 elements per thread
// ---------------------------------------------------------------------------
__global__ void __launch_bounds__(256)
k_split(const float* __restrict__ src, __nv_bfloat16* __restrict__ hi,
        __nv_bfloat16* __restrict__ lo, int n)
{
    for (int i = (blockIdx.x * 256 + threadIdx.x) * 4; i < n; i += gridDim.x * 1024) {
        float4 v = *(const float4*)(src + i);
        __nv_bfloat162 h2a, l2a, h2b, l2b;
        split2(v.x, v.y, h2a, l2a);
        split2(v.z, v.w, h2b, l2b);
        __nv_bfloat162* ph = (__nv_bfloat162*)(hi + i);
        ph[0] = h2a; ph[1] = h2b;
        __nv_bfloat162* pl = (__nv_bfloat162*)(lo + i);
        pl[0] = l2a; pl[1] = l2b;
    }
}

// One launch splits all 4 weight matrices (stacked Q,K,V,O) from 4 src ptrs.
__global__ void __launch_bounds__(256)
k_split_w(const float* __restrict__ s0, const float* __restrict__ s1,
          const float* __restrict__ s2, const float* __restrict__ s3,
          __nv_bfloat16* __restrict__ hi, __nv_bfloat16* __restrict__ lo)
{
    const int i = (blockIdx.x * 256 + threadIdx.x) * 4;   // over 4*DIM*DIM
    const int w = i >> 20;                                // DIM*DIM = 1<<20
    const int off = i & (DIM*DIM - 1);
    const float* src = (w == 0) ? s0 : (w == 1) ? s1 : (w == 2) ? s2 : s3;
    float4 v = *(const float4*)(src + off);
    __nv_bfloat162 h2a, l2a, h2b, l2b;
    split2(v.x, v.y, h2a, l2a);
    split2(v.z, v.w, h2b, l2b);
    __nv_bfloat162* ph = (__nv_bfloat162*)(hi + i);
    ph[0] = h2a; ph[1] = h2b;
    __nv_bfloat162* pl = (__nv_bfloat162*)(lo + i);
    pl[0] = l2a; pl[1] = l2b;
}

// ---------------------------------------------------------------------------
// Causal row softmax, register-cached: one global read, one exp pass, one
// write. Output bf16 hi/lo, zero-padded to the next 128 boundary (PV K-bound).
// ---------------------------------------------------------------------------
__global__ void __launch_bounds__(256)
k_softmax(const float* __restrict__ Pf, __nv_bfloat16* __restrict__ Phi,
          __nv_bfloat16* __restrict__ Plo, int S)
{
    const int b = blockIdx.z;
    const int row = blockIdx.x;
    const float* r = Pf + ((size_t)b * S + row) * S;
    __nv_bfloat16* oh = Phi + ((size_t)b * S + row) * S;
    __nv_bfloat16* ol = Plo + ((size_t)b * S + row) * S;
    const int len = row + 1;
    const int tid = threadIdx.x;

    __shared__ float red[8];

    float xv[8];
    float m = -INFINITY;
    #pragma unroll
    for (int j = 0; j < 8; ++j) {
        const int i = tid + j * 256;
        if (i < len) { xv[j] = r[i]; m = fmaxf(m, xv[j]); }
    }
    #pragma unroll
    for (int o = 16; o; o >>= 1) m = fmaxf(m, __shfl_xor_sync(0xffffffffu, m, o));
    if ((tid & 31) == 0) red[tid >> 5] = m;
    __syncthreads();
    float mm = -INFINITY;
    #pragma unroll
    for (int i = 0; i < 8; ++i) mm = fmaxf(mm, red[i]);
    __syncthreads();

    float ev[8];
    float s = 0.f;
    #pragma unroll
    for (int j = 0; j < 8; ++j) {
        const int i = tid + j * 256;
        if (i < len) { ev[j] = __expf(xv[j] - mm); s += ev[j]; }
    }
    #pragma unroll
    for (int o = 16; o; o >>= 1) s += __shfl_xor_sync(0xffffffffu, s, o);
    if ((tid & 31) == 0) red[tid >> 5] = s;
    __syncthreads();
    float ss = 0.f;
    #pragma unroll
    for (int i = 0; i < 8; ++i) ss += red[i];
    const float inv = 1.f / ss;

    #pragma unroll
    for (int j = 0; j < 8; ++j) {
        const int i = tid + j * 256;
        if (i < len) {
            float p = ev[j] * inv;
            __nv_bfloat16 h = __float2bfloat16(p);
            oh[i] = h;
            ol[i] = __float2bfloat16(p - __bfloat162float(h));
        }
    }
    const int zend = ((row >> 7) + 1) << 7;   // next 128 boundary
    for (int i = len + tid; i < zend; i += 256) {
        oh[i] = __float2bfloat16(0.f);
        ol[i] = __float2bfloat16(0.f);
    }
}

// ---------------------------------------------------------------------------
extern "C" void kernel_launch(void* const* d_in, const int* in_sizes, int n_in,
                              void* d_out, int out_size)
{
    const float* x  = (const float*)d_in[0];
    const float* WQ = (const float*)d_in[1];
    const float* WK = (const float*)d_in[2];
    const float* WV = (const float*)d_in[3];
    const float* WO = (const float*)d_in[4];
    const float* bO = (const float*)d_in[5];
    float* out = (float*)d_out;

    __nv_bfloat16 *xhi, *xlo, *Whi, *Wlo;
    __nv_bfloat16 *Qhi, *Qlo, *Khi, *Klo, *Vthi, *Vtlo, *Phi, *Plo, *Ohi, *Olo;
    float* Pf;
    cudaGetSymbolAddress((void**)&xhi, g_xhi);   cudaGetSymbolAddress((void**)&xlo, g_xlo);
    cudaGetSymbolAddress((void**)&Whi, g_Whi);   cudaGetSymbolAddress((void**)&Wlo, g_Wlo);
    cudaGetSymbolAddress((void**)&Qhi, g_Qhi);   cudaGetSymbolAddress((void**)&Qlo, g_Qlo);
    cudaGetSymbolAddress((void**)&Khi, g_Khi);   cudaGetSymbolAddress((void**)&Klo, g_Klo);
    cudaGetSymbolAddress((void**)&Vthi, g_Vthi); cudaGetSymbolAddress((void**)&Vtlo, g_Vtlo);
    cudaGetSymbolAddress((void**)&Phi, g_Phi);   cudaGetSymbolAddress((void**)&Plo, g_Plo);
    cudaGetSymbolAddress((void**)&Ohi, g_Ohi);   cudaGetSymbolAddress((void**)&Olo, g_Olo);
    cudaGetSymbolAddress((void**)&Pf, g_Pf);

    cudaFuncSetAttribute(k_tc<3,false,false,false,false,8>, cudaFuncAttributeMaxDynamicSharedMemorySize, SMEM_BYTES);
    cudaFuncSetAttribute(k_tc<0,true ,false,false,false,8>, cudaFuncAttributeMaxDynamicSharedMemorySize, SMEM_BYTES);
    cudaFuncSetAttribute(k_tc<1,false,true ,false,true ,8>, cudaFuncAttributeMaxDynamicSharedMemorySize, SMEM_BYTES);
    cudaFuncSetAttribute(k_tc<0,false,false,true ,false,8>, cudaFuncAttributeMaxDynamicSharedMemorySize, SMEM_BYTES);

    // 1. Split inputs to bf16 hi/lo: x (launch 1), all 4 weights (launch 2)
    k_split<<<(MROWS*DIM/4 + 255)/256, 256>>>(x, xhi, xlo, MROWS*DIM);
    k_split_w<<<(4*DIM*DIM/4 + 255)/256, 256>>>(WQ, WK, WV, WO, Whi, Wlo);

    // 2. Merged QKV projection (config B; packed epilogue stores)
    k_tc<3,false,false,false,false,8><<<dim3(3*DIM/128, MROWS/128, 1), 128, SMEM_BYTES>>>(
        xhi, xlo, Whi, Wlo, nullptr, nullptr, nullptr, nullptr,
        3*DIM, DIM, 0, 0, 0);

    // 3. Causal scores (config B), exact triangular grid, longest-first
    k_tc<0,true,false,false,false,8><<<dim3(136, 1, BATCH), 128, SMEM_BYTES>>>(
        Qhi, Qlo, Khi, Klo, Pf, nullptr, nullptr, nullptr,
        SEQ, DIM, (long long)SEQ*DIM, (long long)SEQ*DIM, (long long)SEQ*SEQ);

    // 4. Softmax (register-cached single-exp, zero-pad to 128 boundary)
    k_softmax<<<dim3(SEQ, 1, BATCH), 256>>>(Pf, Phi, Plo, SEQ);

    // 5. PV (config B), K bounded at causal tile edge; longest blocks first
    k_tc<1,false,true,false,true,8><<<dim3(DIM/128, SEQ/128, BATCH), 128, SMEM_BYTES>>>(
        Phi, Plo, Vthi, Vtlo, nullptr, Ohi, Olo, nullptr,
        DIM, SEQ, (long long)SEQ*SEQ, (long long)DIM*SEQ, (long long)SEQ*DIM);

    // 6. Output projection + bias (config B, fp32 out)
    k_tc<0,false,false,true,false,8><<<dim3(DIM/128, MROWS/128, 1), 128, SMEM_BYTES>>>(
        Ohi, Olo, Whi + 3*DIM*DIM, Wlo + 3*DIM*DIM, out, nullptr, nullptr, bO,
        DIM, DIM, 0, 0, 0);
}

// round 14
// speedup vs baseline: 1.0401x; 1.0401x over previous
#include <cuda_runtime.h>
#include <cuda_bf16.h>
#include <math.h>
#include <stdint.h>

#define BATCH 4
#define SEQ   2048
#define DIM   1024
#define MROWS (BATCH*SEQ)   // 8192

// ---------------------------------------------------------------------------
// Scratch (__device__ globals; runtime allocation is forbidden)
// ---------------------------------------------------------------------------
__device__ __nv_bfloat16 g_xhi[MROWS*DIM],  g_xlo[MROWS*DIM];
__device__ __nv_bfloat16 g_Whi[4*DIM*DIM],  g_Wlo[4*DIM*DIM];   // stacked Q,K,V,O
__device__ __nv_bfloat16 g_Qhi[MROWS*DIM],  g_Qlo[MROWS*DIM];
__device__ __nv_bfloat16 g_Khi[MROWS*DIM],  g_Klo[MROWS*DIM];
__device__ __nv_bfloat16 g_Vthi[MROWS*DIM], g_Vtlo[MROWS*DIM];  // [B, D, S]
__device__ float         g_Pf[(size_t)BATCH*SEQ*SEQ];
__device__ __nv_bfloat16 g_Phi[(size_t)BATCH*SEQ*SEQ], g_Plo[(size_t)BATCH*SEQ*SEQ];
__device__ __nv_bfloat16 g_Ohi[MROWS*DIM],  g_Olo[MROWS*DIM];

// ---------------------------------------------------------------------------
// Helpers
// ---------------------------------------------------------------------------
__device__ __forceinline__ uint32_t smem_u32(const void* p) {
    uint32_t a;
    asm("{ .reg .u64 t; cvta.to.shared.u64 t, %1; cvt.u32.u64 %0, t; }" : "=r"(a) : "l"(p));
    return a;
}

// XOR swizzle for 64B-row tiles (8 rows x 64B atom): conflict-free ldmatrix
#define SWZ64(off) ((uint32_t)(off) ^ (((uint32_t)(off) >> 3) & 0x30))

#define CP16(dst, src) \
    asm volatile("cp.async.cg.shared.global [%0], [%1], 16;" :: "r"(dst), "l"(src))
#define CPCOMMIT() asm volatile("cp.async.commit_group;" ::: "memory")
#define CPWAIT(n)  asm volatile("cp.async.wait_group %0;" :: "n"(n) : "memory")

__device__ __forceinline__ void ldm4(uint32_t* r, uint32_t addr) {
    asm volatile("ldmatrix.sync.aligned.m8n8.x4.shared.b16 {%0,%1,%2,%3}, [%4];"
        : "=r"(r[0]), "=r"(r[1]), "=r"(r[2]), "=r"(r[3]) : "r"(addr));
}

__device__ __forceinline__ void mma16816(float* c, const uint32_t* a, const uint32_t* b) {
    asm volatile("mma.sync.aligned.m16n8k16.row.col.f32.bf16.bf16.f32 "
        "{%0,%1,%2,%3}, {%4,%5,%6,%7}, {%8,%9}, {%0,%1,%2,%3};"
        : "+f"(c[0]), "+f"(c[1]), "+f"(c[2]), "+f"(c[3])
        : "r"(a[0]), "r"(a[1]), "r"(a[2]), "r"(a[3]), "r"(b[0]), "r"(b[1]));
}

// pack two fp32 into bf16x2 + residual bf16x2
__device__ __forceinline__ void split2(float v0, float v1,
                                       __nv_bfloat162& hi2, __nv_bfloat162& lo2) {
    __nv_bfloat16 h0 = __float2bfloat16(v0), h1 = __float2bfloat16(v1);
    hi2 = __nv_bfloat162(h0, h1);
    lo2 = __nv_bfloat162(__float2bfloat16(v0 - __bfloat162float(h0)),
                         __float2bfloat16(v1 - __bfloat162float(h1)));
}

// ---------------------------------------------------------------------------
// Tensor-core GEMM: C(128x128 tiles) = A * B^T, 3-MMA bf16 split precision.
// NTN = n-tiles (8 cols each) per warp:
//   NTN=4: 256 thr, 8 warps 2x4, warp 64x32  (epilogue-heavy: QKV, PV)
//   NTN=8: 128 thr, 4 warps 2x2, warp 64x64  (mainloop-bound: scores, out)
// 2 CTAs/SM in both configs.
// EPI: 0 = fp32 out (+bias), 1 = bf16 hi/lo out, 3 = QKV-routed (Q/K direct,
//      V transposed via smem staging). hi/lo stores are packed bf16x2.
// CAUSAL: exact triangular grid decode, longest-first
// ---------------------------------------------------------------------------
#define STAGE_BYTES 32768
#define OFF_AHI 0
#define OFF_ALO 8192
#define OFF_BHI 16384
#define OFF_BLO 24576
#define SMEM_BYTES 65536     // 2 stages
#define TPITCH 136           // transpose staging pitch (bf16 elements)

template<int EPI, bool CAUSAL, bool KBOUND, bool HASBIAS, bool REV, int NTN>
__global__ void __launch_bounds__((NTN==4 ? 256 : 128), 2)
k_tc(const __nv_bfloat16* __restrict__ Ahi, const __nv_bfloat16* __restrict__ Alo,
     const __nv_bfloat16* __restrict__ Bhi, const __nv_bfloat16* __restrict__ Blo,
     float* __restrict__ Cf, __nv_bfloat16* __restrict__ Chi, __nv_bfloat16* __restrict__ Clo,
     const float* __restrict__ bias,
     int N, int Kdim, long long sA, long long sB, long long sC)
{
    constexpr int NT = (NTN==4 ? 256 : 128);   // threads
    constexpr int WNOFF = NTN * 8;             // warp n-span
    int m0, n0;
    if (CAUSAL) {
        // longest-first: reverse the triangular index
        const int tix = (int)gridDim.x - 1 - (int)blockIdx.x;
        int mb = (int)((sqrtf(8.f * tix + 1.f) - 1.f) * 0.5f + 1e-4f);
        while ((mb + 1) * (mb + 2) / 2 <= tix) ++mb;
        while (mb * (mb + 1) / 2 > tix) --mb;
        const int nb = tix - mb * (mb + 1) / 2;
        m0 = mb * 128;
        n0 = nb * 128;
    } else {
        const int by = REV ? (gridDim.y - 1 - blockIdx.y) : blockIdx.y;
        m0 = by * 128;
        n0 = blockIdx.x * 128;
    }
    const long long b = blockIdx.z;
    Ahi += b * sA; Alo += b * sA;
    Bhi += b * sB; Blo += b * sB;

    extern __shared__ char smem[];
    const uint32_t sb = smem_u32(smem);
    const int tid = threadIdx.x, lane = tid & 31, wid = tid >> 5;
    const int wm = wid & 1, wn = wid >> 1;     // warp tile 64(m) x WNOFF(n)

    const int kend = KBOUND ? (m0 + 128) : Kdim;
    const int nchunk = kend >> 5;              // BK = 32

    float acc[4][NTN][4];
    #pragma unroll
    for (int i = 0; i < 4; ++i)
        #pragma unroll
        for (int j = 0; j < NTN; ++j)
            #pragma unroll
            for (int r = 0; r < 4; ++r) acc[i][j][r] = 0.f;

    // stage loader: 4 tiles of 128 rows x 64B, SWZ64 layout, cp.async 16B
    auto load_stage = [&](int c, int s) {
        const int k0 = c << 5;
        const uint32_t sbase = sb + s * STAGE_BYTES;
        #pragma unroll
        for (int h = 0; h < 512/NT; ++h) {
            const int idx = tid + h * NT;      // 0..511
            const int row = idx >> 2, ch = idx & 3;
            const uint32_t so = SWZ64(row * 64 + ch * 16);
            const size_t gA = (size_t)(m0 + row) * Kdim + k0 + ch * 8;
            const size_t gB = (size_t)(n0 + row) * Kdim + k0 + ch * 8;
            CP16(sbase + OFF_AHI + so, Ahi + gA);
            CP16(sbase + OFF_ALO + so, Alo + gA);
            CP16(sbase + OFF_BHI + so, Bhi + gB);
            CP16(sbase + OFF_BLO + so, Blo + gB);
        }
    };

    load_stage(0, 0); CPCOMMIT();

    // Single-barrier pipeline: wait(c) -> barrier -> issue(c+1) -> consume(c).
    for (int c = 0; c < nchunk; ++c) {
        CPWAIT(0);
        __syncthreads();
        if (c + 1 < nchunk) { load_stage(c + 1, (c + 1) & 1); CPCOMMIT(); }

        const uint32_t sA = sb + (c & 1) * STAGE_BYTES;
        #pragma unroll
        for (int kk = 0; kk < 32; kk += 16) {
            // B fragments: NTN nt tiles (hi+lo)
            uint32_t bhi[NTN][2], blo[NTN][2];
            const int brow  = (lane & 7) + ((lane & 16) ? 8 : 0);
            const int bkoff = (lane & 8) ? 8 : 0;
            #pragma unroll
            for (int np = 0; np < NTN/2; ++np) {
                const uint32_t off = SWZ64((wn*WNOFF + np*16 + brow) * 64 + (kk + bkoff) * 2);
                uint32_t t4[4];
                ldm4(t4, sA + OFF_BHI + off);
                bhi[np*2][0] = t4[0]; bhi[np*2][1] = t4[1];
                bhi[np*2+1][0] = t4[2]; bhi[np*2+1][1] = t4[3];
                ldm4(t4, sA + OFF_BLO + off);
                blo[np*2][0] = t4[0]; blo[np*2][1] = t4[1];
                blo[np*2+1][0] = t4[2]; blo[np*2+1][1] = t4[3];
            }
            // A fragments: 4 mt tiles, hi and lo in separate regs
            const int arow  = lane & 15;
            const int akoff = (lane >> 4) << 3;
            uint32_t ahi[4][4], alo[4][4];
            #pragma unroll
            for (int mt = 0; mt < 4; ++mt) {
                const uint32_t off = SWZ64((wm*64 + mt*16 + arow) * 64 + (kk + akoff) * 2);
                ldm4(ahi[mt], sA + OFF_AHI + off);
                ldm4(alo[mt], sA + OFF_ALO + off);
            }
            // pass 1: hi*hi
            #pragma unroll
            for (int mt = 0; mt < 4; ++mt)
                #pragma unroll
                for (int nt = 0; nt < NTN; ++nt)
                    mma16816(acc[mt][nt], ahi[mt], bhi[nt]);
            // pass 2: hi*lo
            #pragma unroll
            for (int mt = 0; mt < 4; ++mt)
                #pragma unroll
                for (int nt = 0; nt < NTN; ++nt)
                    mma16816(acc[mt][nt], ahi[mt], blo[nt]);
            // pass 3: lo*hi
            #pragma unroll
            for (int mt = 0; mt < 4; ++mt)
                #pragma unroll
                for (int nt = 0; nt < NTN; ++nt)
                    mma16816(acc[mt][nt], alo[mt], bhi[nt]);
        }
    }

    // Epilogue. C frag: (c0,c1) row g cols t*2,t*2+1; (c2,c3) row g+8.
    const int g = lane >> 2, t = lane & 3;
    const bool vpath = (EPI == 3) && (n0 >= 2*DIM);
    if (vpath) {
        // V projection: smem-staged transpose [n][m], coalesced stores along s.
        __syncthreads();   // laggards may still be reading stage smem
        __nv_bfloat16* tsm = (__nv_bfloat16*)smem;
        const int bb = m0 >> 11, sbase_s = m0 & 2047;
        const int nvl0 = n0 - 2*DIM;
        #pragma unroll
        for (int comp = 0; comp < 2; ++comp) {
            #pragma unroll
            for (int mt = 0; mt < 4; ++mt)
                #pragma unroll
                for (int nt = 0; nt < NTN; ++nt)
                    #pragma unroll
                    for (int h = 0; h < 2; ++h) {
                        const int ml = wm*64 + mt*16 + g + h*8;
                        const int nl = wn*WNOFF + nt*8 + t*2;
                        float v0 = acc[mt][nt][h*2], v1 = acc[mt][nt][h*2+1];
                        __nv_bfloat162 hi2, lo2;
                        split2(v0, v1, hi2, lo2);
                        __nv_bfloat162 o2 = (comp == 0) ? hi2 : lo2;
                        tsm[(size_t)nl * TPITCH + ml]     = o2.x;
                        tsm[(size_t)(nl+1) * TPITCH + ml] = o2.y;
                    }
            __syncthreads();
            __nv_bfloat16* dst = (comp == 0) ? g_Vthi : g_Vtlo;
            // NT threads cover 128 rows x (NT/128) col-chunks
            constexpr int CHW = 16384 / NT;    // bf16 per thread (64 or 128)
            const int nl = tid / (NT/128), mh = (tid % (NT/128)) * CHW;
            const __nv_bfloat16* srow = tsm + (size_t)nl * TPITCH + mh;
            __nv_bfloat16* drow = dst + ((size_t)bb * DIM + (nvl0 + nl)) * SEQ + sbase_s + mh;
            #pragma unroll
            for (int q = 0; q < CHW/8; ++q)
                *(uint4*)(drow + q*8) = *(const uint4*)(srow + q*8);
            __syncthreads();
        }
        return;
    }
    #pragma unroll
    for (int mt = 0; mt < 4; ++mt)
        #pragma unroll
        for (int nt = 0; nt < NTN; ++nt)
            #pragma unroll
            for (int h = 0; h < 2; ++h) {
                const int m  = m0 + wm*64 + mt*16 + g + h*8;
                const int nb = n0 + wn*WNOFF + nt*8 + t*2;
                float v0 = acc[mt][nt][h*2], v1 = acc[mt][nt][h*2+1];
                if (EPI == 0) {
                    if (HASBIAS) { v0 += bias[nb]; v1 += bias[nb+1]; }
                    float* o = Cf + b*sC + (size_t)m*N + nb;
                    o[0] = v0; o[1] = v1;
                } else if (EPI == 1) {
                    const size_t base = (size_t)(b*sC) + (size_t)m*N + nb;
                    __nv_bfloat162 hi2, lo2;
                    split2(v0, v1, hi2, lo2);
                    *(__nv_bfloat162*)(Chi + base) = hi2;
                    *(__nv_bfloat162*)(Clo + base) = lo2;
                } else {  // EPI==3, Q/K route
                    const int which = nb >> 10;         // 0=Q, 1=K
                    const int nl = nb & 1023;
                    __nv_bfloat16* dh = which ? g_Khi : g_Qhi;
                    __nv_bfloat16* dl = which ? g_Klo : g_Qlo;
                    const size_t base = (size_t)m * DIM + nl;
                    __nv_bfloat162 hi2, lo2;
                    split2(v0, v1, hi2, lo2);
                    *(__nv_bfloat162*)(dh + base) = hi2;
                    *(__nv_bfloat162*)(dl + base) = lo2;
                }
            }
}

// ---------------------------------------------------------------------------
// fp32 -> (bf16 hi, bf16 lo) split, grid-strided, 4 elements per thread
// ---------------------------------------------------------------------------
__global__ void __launch_bounds__(256)
k_split(const float* __restrict__ src, __nv_bfloat16* __restrict__ hi,
        __nv_bfloat16* __restrict__ lo, int n)
{
    for (int i = (blockIdx.x * 256 + threadIdx.x) * 4; i < n; i += gridDim.x * 1024) {
        float4 v = *(const float4*)(src + i);
        __nv_bfloat162 h2a, l2a, h2b, l2b;
        split2(v.x, v.y, h2a, l2a);
        split2(v.z, v.w, h2b, l2b);
        __nv_bfloat162* ph = (__nv_bfloat162*)(hi + i);
        ph[0] = h2a; ph[1] = h2b;
        __nv_bfloat162* pl = (__nv_bfloat162*)(lo + i);
        pl[0] = l2a; pl[1] = l2b;
    }
}

// One launch splits all 4 weight matrices (stacked Q,K,V,O) from 4 src ptrs.
__global__ void __launch_bounds__(256)
k_split_w(const float* __restrict__ s0, const float* __restrict__ s1,
          const float* __restrict__ s2, const float* __restrict__ s3,
          __nv_bfloat16* __restrict__ hi, __nv_bfloat16* __restrict__ lo)
{
    const int i = (blockIdx.x * 256 + threadIdx.x) * 4;   // over 4*DIM*DIM
    const int w = i >> 20;                                // DIM*DIM = 1<<20
    const int off = i & (DIM*DIM - 1);
    const float* src = (w == 0) ? s0 : (w == 1) ? s1 : (w == 2) ? s2 : s3;
    float4 v = *(const float4*)(src + off);
    __nv_bfloat162 h2a, l2a, h2b, l2b;
    split2(v.x, v.y, h2a, l2a);
    split2(v.z, v.w, h2b, l2b);
    __nv_bfloat162* ph = (__nv_bfloat162*)(hi + i);
    ph[0] = h2a; ph[1] = h2b;
    __nv_bfloat162* pl = (__nv_bfloat162*)(lo + i);
    pl[0] = l2a; pl[1] = l2b;
}

// ---------------------------------------------------------------------------
// Causal row softmax, vectorized: float4 logit loads (row buffer is full S,
// masked beyond len), one exp pass, packed bf16x2 weight stores zero-padded
// to the next 128 boundary (PV K-bound). 256 threads, 4 contiguous elems x 2.
// ---------------------------------------------------------------------------
__global__ void __launch_bounds__(256)
k_softmax(const float* __restrict__ Pf, __nv_bfloat16* __restrict__ Phi,
          __nv_bfloat16* __restrict__ Plo, int S)
{
    const int b = blockIdx.z;
    const int row = blockIdx.x;
    const float* r = Pf + ((size_t)b * S + row) * S;
    __nv_bfloat16* oh = Phi + ((size_t)b * S + row) * S;
    __nv_bfloat16* ol = Plo + ((size_t)b * S + row) * S;
    const int len = row + 1;
    const int zend = ((row >> 7) + 1) << 7;   // next 128 boundary
    const int tid = threadIdx.x;

    __shared__ float red[8];

    float4 xv[2];
    float m = -INFINITY;
    #pragma unroll
    for (int j = 0; j < 2; ++j) {
        const int base = j * 1024 + tid * 4;
        xv[j] = *(const float4*)(r + base);   // always in-bounds (row len S)
        if (base + 0 < len) m = fmaxf(m, xv[j].x);
        if (base + 1 < len) m = fmaxf(m, xv[j].y);
        if (base + 2 < len) m = fmaxf(m, xv[j].z);
        if (base + 3 < len) m = fmaxf(m, xv[j].w);
    }
    #pragma unroll
    for (int o = 16; o; o >>= 1) m = fmaxf(m, __shfl_xor_sync(0xffffffffu, m, o));
    if ((tid & 31) == 0) red[tid >> 5] = m;
    __syncthreads();
    float mm = -INFINITY;
    #pragma unroll
    for (int i = 0; i < 8; ++i) mm = fmaxf(mm, red[i]);
    __syncthreads();

    float4 ev[2];
    float s = 0.f;
    #pragma unroll
    for (int j = 0; j < 2; ++j) {
        const int base = j * 1024 + tid * 4;
        ev[j].x = (base + 0 < len) ? __expf(xv[j].x - mm) : 0.f;
        ev[j].y = (base + 1 < len) ? __expf(xv[j].y - mm) : 0.f;
        ev[j].z = (base + 2 < len) ? __expf(xv[j].z - mm) : 0.f;
        ev[j].w = (base + 3 < len) ? __expf(xv[j].w - mm) : 0.f;
        s += ev[j].x + ev[j].y + ev[j].z + ev[j].w;
    }
    #pragma unroll
    for (int o = 16; o; o >>= 1) s += __shfl_xor_sync(0xffffffffu, s, o);
    if ((tid & 31) == 0) red[tid >> 5] = s;
    __syncthreads();
    float ss = 0.f;
    #pragma unroll
    for (int i = 0; i < 8; ++i) ss += red[i];
    const float inv = 1.f / ss;

    // Store [0, zend): normalized weights for i<len, zeros for [len, zend).
    // base is a multiple of 4 and zend a multiple of 128, so 4-wide groups
    // never straddle zend.
    #pragma unroll
    for (int j = 0; j < 2; ++j) {
        const int base = j * 1024 + tid * 4;
        if (base >= zend) continue;
        float p0 = ev[j].x * inv, p1 = ev[j].y * inv;
        float p2 = ev[j].z * inv, p3 = ev[j].w * inv;
        __nv_bfloat162 h2a, l2a, h2b, l2b;
        split2(p0, p1, h2a, l2a);
        split2(p2, p3, h2b, l2b);
        __nv_bfloat162* ph = (__nv_bfloat162*)(oh + base);
        ph[0] = h2a; ph[1] = h2b;
        __nv_bfloat162* pl = (__nv_bfloat162*)(ol + base);
        pl[0] = l2a; pl[1] = l2b;
    }
}

// ---------------------------------------------------------------------------
extern "C" void kernel_launch(void* const* d_in, const int* in_sizes, int n_in,
                              void* d_out, int out_size)
{
    const float* x  = (const float*)d_in[0];
    const float* WQ = (const float*)d_in[1];
    const float* WK = (const float*)d_in[2];
    const float* WV = (const float*)d_in[3];
    const float* WO = (const float*)d_in[4];
    const float* bO = (const float*)d_in[5];
    float* out = (float*)d_out;

    __nv_bfloat16 *xhi, *xlo, *Whi, *Wlo;
    __nv_bfloat16 *Qhi, *Qlo, *Khi, *Klo, *Vthi, *Vtlo, *Phi, *Plo, *Ohi, *Olo;
    float* Pf;
    cudaGetSymbolAddress((void**)&xhi, g_xhi);   cudaGetSymbolAddress((void**)&xlo, g_xlo);
    cudaGetSymbolAddress((void**)&Whi, g_Whi);   cudaGetSymbolAddress((void**)&Wlo, g_Wlo);
    cudaGetSymbolAddress((void**)&Qhi, g_Qhi);   cudaGetSymbolAddress((void**)&Qlo, g_Qlo);
    cudaGetSymbolAddress((void**)&Khi, g_Khi);   cudaGetSymbolAddress((void**)&Klo, g_Klo);
    cudaGetSymbolAddress((void**)&Vthi, g_Vthi); cudaGetSymbolAddress((void**)&Vtlo, g_Vtlo);
    cudaGetSymbolAddress((void**)&Phi, g_Phi);   cudaGetSymbolAddress((void**)&Plo, g_Plo);
    cudaGetSymbolAddress((void**)&Ohi, g_Ohi);   cudaGetSymbolAddress((void**)&Olo, g_Olo);
    cudaGetSymbolAddress((void**)&Pf, g_Pf);

    cudaFuncSetAttribute(k_tc<3,false,false,false,false,4>, cudaFuncAttributeMaxDynamicSharedMemorySize, SMEM_BYTES);
    cudaFuncSetAttribute(k_tc<0,true ,false,false,false,8>, cudaFuncAttributeMaxDynamicSharedMemorySize, SMEM_BYTES);
    cudaFuncSetAttribute(k_tc<1,false,true ,false,true ,4>, cudaFuncAttributeMaxDynamicSharedMemorySize, SMEM_BYTES);
    cudaFuncSetAttribute(k_tc<0,false,false,true ,false,8>, cudaFuncAttributeMaxDynamicSharedMemorySize, SMEM_BYTES);

    // 1. Split inputs to bf16 hi/lo: x (launch 1), all 4 weights (launch 2)
    k_split<<<(MROWS*DIM/4 + 255)/256, 256>>>(x, xhi, xlo, MROWS*DIM);
    k_split_w<<<(4*DIM*DIM/4 + 255)/256, 256>>>(WQ, WK, WV, WO, Whi, Wlo);

    // 2. Merged QKV projection (config A: 256 thr, epilogue-heavy)
    k_tc<3,false,false,false,false,4><<<dim3(3*DIM/128, MROWS/128, 1), 256, SMEM_BYTES>>>(
        xhi, xlo, Whi, Wlo, nullptr, nullptr, nullptr, nullptr,
        3*DIM, DIM, 0, 0, 0);

    // 3. Causal scores (config B), exact triangular grid, longest-first
    k_tc<0,true,false,false,false,8><<<dim3(136, 1, BATCH), 128, SMEM_BYTES>>>(
        Qhi, Qlo, Khi, Klo, Pf, nullptr, nullptr, nullptr,
        SEQ, DIM, (long long)SEQ*DIM, (long long)SEQ*DIM, (long long)SEQ*SEQ);

    // 4. Softmax (vectorized float4 loads, packed bf16x2 stores)
    k_softmax<<<dim3(SEQ, 1, BATCH), 256>>>(Pf, Phi, Plo, SEQ);

    // 5. PV (config A), K bounded at causal tile edge; longest blocks first
    k_tc<1,false,true,false,true,4><<<dim3(DIM/128, SEQ/128, BATCH), 256, SMEM_BYTES>>>(
        Phi, Plo, Vthi, Vtlo, nullptr, Ohi, Olo, nullptr,
        DIM, SEQ, (long long)SEQ*SEQ, (long long)DIM*SEQ, (long long)SEQ*DIM);

    // 6. Output projection + bias (config B, fp32 out)
    k_tc<0,false,false,true,false,8><<<dim3(DIM/128, MROWS/128, 1), 128, SMEM_BYTES>>>(
        Ohi, Olo, Whi + 3*DIM*DIM, Wlo + 3*DIM*DIM, out, nullptr, nullptr, bO,
        DIM, DIM, 0, 0, 0);
}

// round 15
// speedup vs baseline: 1.1529x; 1.1085x over previous
#include <cuda_runtime.h>
#include <cuda_bf16.h>
#include <math.h>
#include <stdint.h>

#define BATCH 4
#define SEQ   2048
#define DIM   1024
#define MROWS (BATCH*SEQ)   // 8192

// ---------------------------------------------------------------------------
// Scratch (__device__ globals; runtime allocation is forbidden)
// ---------------------------------------------------------------------------
__device__ __nv_bfloat16 g_xhi[MROWS*DIM],  g_xlo[MROWS*DIM];
__device__ __nv_bfloat16 g_Whi[3*DIM*DIM],  g_Wlo[3*DIM*DIM];   // stacked Wq,Wk,Wc
__device__ __nv_bfloat16 g_Wohi[DIM*DIM],   g_Wolo[DIM*DIM];    // Wo split
__device__ __nv_bfloat16 g_Wvthi[DIM*DIM],  g_Wvtlo[DIM*DIM];   // Wv^T split
__device__ __nv_bfloat16 g_Qhi[MROWS*DIM],  g_Qlo[MROWS*DIM];
__device__ __nv_bfloat16 g_Khi[MROWS*DIM],  g_Klo[MROWS*DIM];
__device__ __nv_bfloat16 g_Vthi[MROWS*DIM], g_Vtlo[MROWS*DIM];  // VW^T: [B, D, S]
__device__ float         g_Pf[(size_t)BATCH*SEQ*SEQ];
__device__ __nv_bfloat16 g_Phi[(size_t)BATCH*SEQ*SEQ], g_Plo[(size_t)BATCH*SEQ*SEQ];

// ---------------------------------------------------------------------------
// Helpers
// ---------------------------------------------------------------------------
__device__ __forceinline__ uint32_t smem_u32(const void* p) {
    uint32_t a;
    asm("{ .reg .u64 t; cvta.to.shared.u64 t, %1; cvt.u32.u64 %0, t; }" : "=r"(a) : "l"(p));
    return a;
}

// XOR swizzle for 64B-row tiles (8 rows x 64B atom): conflict-free ldmatrix
#define SWZ64(off) ((uint32_t)(off) ^ (((uint32_t)(off) >> 3) & 0x30))

#define CP16(dst, src) \
    asm volatile("cp.async.cg.shared.global [%0], [%1], 16;" :: "r"(dst), "l"(src))
#define CPCOMMIT() asm volatile("cp.async.commit_group;" ::: "memory")
#define CPWAIT(n)  asm volatile("cp.async.wait_group %0;" :: "n"(n) : "memory")

__device__ __forceinline__ void ldm4(uint32_t* r, uint32_t addr) {
    asm volatile("ldmatrix.sync.aligned.m8n8.x4.shared.b16 {%0,%1,%2,%3}, [%4];"
        : "=r"(r[0]), "=r"(r[1]), "=r"(r[2]), "=r"(r[3]) : "r"(addr));
}

__device__ __forceinline__ void mma16816(float* c, const uint32_t* a, const uint32_t* b) {
    asm volatile("mma.sync.aligned.m16n8k16.row.col.f32.bf16.bf16.f32 "
        "{%0,%1,%2,%3}, {%4,%5,%6,%7}, {%8,%9}, {%0,%1,%2,%3};"
        : "+f"(c[0]), "+f"(c[1]), "+f"(c[2]), "+f"(c[3])
        : "r"(a[0]), "r"(a[1]), "r"(a[2]), "r"(a[3]), "r"(b[0]), "r"(b[1]));
}

// pack two fp32 into bf16x2 + residual bf16x2
__device__ __forceinline__ void split2(float v0, float v1,
                                       __nv_bfloat162& hi2, __nv_bfloat162& lo2) {
    __nv_bfloat16 h0 = __float2bfloat16(v0), h1 = __float2bfloat16(v1);
    hi2 = __nv_bfloat162(h0, h1);
    lo2 = __nv_bfloat162(__float2bfloat16(v0 - __bfloat162float(h0)),
                         __float2bfloat16(v1 - __bfloat162float(h1)));
}

// ---------------------------------------------------------------------------
// Tensor-core GEMM: C(128x128 tiles) = A * B^T, 3-MMA bf16 split precision.
// NTN = n-tiles (8 cols each) per warp:
//   NTN=4: 256 thr, 8 warps 2x4, warp 64x32  (epilogue-heavy: QKV)
//   NTN=8: 128 thr, 4 warps 2x2, warp 64x64  (mainloop-bound: scores, PV, Wc)
// 2 CTAs/SM in both configs.
// EPI: 0 = fp32 out (+bias), 1 = bf16 hi/lo out, 3 = QKV-routed (Q/K direct,
//      V-slot transposed via smem staging). hi/lo stores are packed bf16x2.
// CAUSAL: exact triangular grid decode, longest-first
// ---------------------------------------------------------------------------
#define STAGE_BYTES 32768
#define OFF_AHI 0
#define OFF_ALO 8192
#define OFF_BHI 16384
#define OFF_BLO 24576
#define SMEM_BYTES 65536     // 2 stages
#define TPITCH 136           // transpose staging pitch (bf16 elements)

template<int EPI, bool CAUSAL, bool KBOUND, bool HASBIAS, bool REV, int NTN>
__global__ void __launch_bounds__((NTN==4 ? 256 : 128), 2)
k_tc(const __nv_bfloat16* __restrict__ Ahi, const __nv_bfloat16* __restrict__ Alo,
     const __nv_bfloat16* __restrict__ Bhi, const __nv_bfloat16* __restrict__ Blo,
     float* __restrict__ Cf, __nv_bfloat16* __restrict__ Chi, __nv_bfloat16* __restrict__ Clo,
     const float* __restrict__ bias,
     int N, int Kdim, long long sA, long long sB, long long sC)
{
    constexpr int NT = (NTN==4 ? 256 : 128);   // threads
    constexpr int WNOFF = NTN * 8;             // warp n-span
    int m0, n0;
    if (CAUSAL) {
        // longest-first: reverse the triangular index
        const int tix = (int)gridDim.x - 1 - (int)blockIdx.x;
        int mb = (int)((sqrtf(8.f * tix + 1.f) - 1.f) * 0.5f + 1e-4f);
        while ((mb + 1) * (mb + 2) / 2 <= tix) ++mb;
        while (mb * (mb + 1) / 2 > tix) --mb;
        const int nb = tix - mb * (mb + 1) / 2;
        m0 = mb * 128;
        n0 = nb * 128;
    } else {
        const int by = REV ? (gridDim.y - 1 - blockIdx.y) : blockIdx.y;
        m0 = by * 128;
        n0 = blockIdx.x * 128;
    }
    const long long b = blockIdx.z;
    Ahi += b * sA; Alo += b * sA;
    Bhi += b * sB; Blo += b * sB;

    extern __shared__ char smem[];
    const uint32_t sb = smem_u32(smem);
    const int tid = threadIdx.x, lane = tid & 31, wid = tid >> 5;
    const int wm = wid & 1, wn = wid >> 1;     // warp tile 64(m) x WNOFF(n)

    const int kend = KBOUND ? (m0 + 128) : Kdim;
    const int nchunk = kend >> 5;              // BK = 32

    float acc[4][NTN][4];
    #pragma unroll
    for (int i = 0; i < 4; ++i)
        #pragma unroll
        for (int j = 0; j < NTN; ++j)
            #pragma unroll
            for (int r = 0; r < 4; ++r) acc[i][j][r] = 0.f;

    // stage loader: 4 tiles of 128 rows x 64B, SWZ64 layout, cp.async 16B
    auto load_stage = [&](int c, int s) {
        const int k0 = c << 5;
        const uint32_t sbase = sb + s * STAGE_BYTES;
        #pragma unroll
        for (int h = 0; h < 512/NT; ++h) {
            const int idx = tid + h * NT;      // 0..511
            const int row = idx >> 2, ch = idx & 3;
            const uint32_t so = SWZ64(row * 64 + ch * 16);
            const size_t gA = (size_t)(m0 + row) * Kdim + k0 + ch * 8;
            const size_t gB = (size_t)(n0 + row) * Kdim + k0 + ch * 8;
            CP16(sbase + OFF_AHI + so, Ahi + gA);
            CP16(sbase + OFF_ALO + so, Alo + gA);
            CP16(sbase + OFF_BHI + so, Bhi + gB);
            CP16(sbase + OFF_BLO + so, Blo + gB);
        }
    };

    load_stage(0, 0); CPCOMMIT();

    // Single-barrier pipeline: wait(c) -> barrier -> issue(c+1) -> consume(c).
    for (int c = 0; c < nchunk; ++c) {
        CPWAIT(0);
        __syncthreads();
        if (c + 1 < nchunk) { load_stage(c + 1, (c + 1) & 1); CPCOMMIT(); }

        const uint32_t sA = sb + (c & 1) * STAGE_BYTES;
        #pragma unroll
        for (int kk = 0; kk < 32; kk += 16) {
            // B fragments: NTN nt tiles (hi+lo)
            uint32_t bhi[NTN][2], blo[NTN][2];
            const int brow  = (lane & 7) + ((lane & 16) ? 8 : 0);
            const int bkoff = (lane & 8) ? 8 : 0;
            #pragma unroll
            for (int np = 0; np < NTN/2; ++np) {
                const uint32_t off = SWZ64((wn*WNOFF + np*16 + brow) * 64 + (kk + bkoff) * 2);
                uint32_t t4[4];
                ldm4(t4, sA + OFF_BHI + off);
                bhi[np*2][0] = t4[0]; bhi[np*2][1] = t4[1];
                bhi[np*2+1][0] = t4[2]; bhi[np*2+1][1] = t4[3];
                ldm4(t4, sA + OFF_BLO + off);
                blo[np*2][0] = t4[0]; blo[np*2][1] = t4[1];
                blo[np*2+1][0] = t4[2]; blo[np*2+1][1] = t4[3];
            }
            // A fragments: 4 mt tiles, hi and lo in separate regs
            const int arow  = lane & 15;
            const int akoff = (lane >> 4) << 3;
            uint32_t ahi[4][4], alo[4][4];
            #pragma unroll
            for (int mt = 0; mt < 4; ++mt) {
                const uint32_t off = SWZ64((wm*64 + mt*16 + arow) * 64 + (kk + akoff) * 2);
                ldm4(ahi[mt], sA + OFF_AHI + off);
                ldm4(alo[mt], sA + OFF_ALO + off);
            }
            // pass 1: hi*hi
            #pragma unroll
            for (int mt = 0; mt < 4; ++mt)
                #pragma unroll
                for (int nt = 0; nt < NTN; ++nt)
                    mma16816(acc[mt][nt], ahi[mt], bhi[nt]);
            // pass 2: hi*lo
            #pragma unroll
            for (int mt = 0; mt < 4; ++mt)
                #pragma unroll
                for (int nt = 0; nt < NTN; ++nt)
                    mma16816(acc[mt][nt], ahi[mt], blo[nt]);
            // pass 3: lo*hi
            #pragma unroll
            for (int mt = 0; mt < 4; ++mt)
                #pragma unroll
                for (int nt = 0; nt < NTN; ++nt)
                    mma16816(acc[mt][nt], alo[mt], bhi[nt]);
        }
    }

    // Epilogue. C frag: (c0,c1) row g cols t*2,t*2+1; (c2,c3) row g+8.
    const int g = lane >> 2, t = lane & 3;
    const bool vpath = (EPI == 3) && (n0 >= 2*DIM);
    if (vpath) {
        // V-slot (x @ Wc^T): smem-staged transpose [n][m], coalesced stores.
        __syncthreads();   // laggards may still be reading stage smem
        __nv_bfloat16* tsm = (__nv_bfloat16*)smem;
        const int bb = m0 >> 11, sbase_s = m0 & 2047;
        const int nvl0 = n0 - 2*DIM;
        #pragma unroll
        for (int comp = 0; comp < 2; ++comp) {
            #pragma unroll
            for (int mt = 0; mt < 4; ++mt)
                #pragma unroll
                for (int nt = 0; nt < NTN; ++nt)
                    #pragma unroll
                    for (int h = 0; h < 2; ++h) {
                        const int ml = wm*64 + mt*16 + g + h*8;
                        const int nl = wn*WNOFF + nt*8 + t*2;
                        float v0 = acc[mt][nt][h*2], v1 = acc[mt][nt][h*2+1];
                        __nv_bfloat162 hi2, lo2;
                        split2(v0, v1, hi2, lo2);
                        __nv_bfloat162 o2 = (comp == 0) ? hi2 : lo2;
                        tsm[(size_t)nl * TPITCH + ml]     = o2.x;
                        tsm[(size_t)(nl+1) * TPITCH + ml] = o2.y;
                    }
            __syncthreads();
            __nv_bfloat16* dst = (comp == 0) ? g_Vthi : g_Vtlo;
            // NT threads cover 128 rows x (NT/128) col-chunks
            constexpr int CHW = 16384 / NT;    // bf16 per thread (64 or 128)
            const int nl = tid / (NT/128), mh = (tid % (NT/128)) * CHW;
            const __nv_bfloat16* srow = tsm + (size_t)nl * TPITCH + mh;
            __nv_bfloat16* drow = dst + ((size_t)bb * DIM + (nvl0 + nl)) * SEQ + sbase_s + mh;
            #pragma unroll
            for (int q = 0; q < CHW/8; ++q)
                *(uint4*)(drow + q*8) = *(const uint4*)(srow + q*8);
            __syncthreads();
        }
        return;
    }
    #pragma unroll
    for (int mt = 0; mt < 4; ++mt)
        #pragma unroll
        for (int nt = 0; nt < NTN; ++nt)
            #pragma unroll
            for (int h = 0; h < 2; ++h) {
                const int m  = m0 + wm*64 + mt*16 + g + h*8;
                const int nb = n0 + wn*WNOFF + nt*8 + t*2;
                float v0 = acc[mt][nt][h*2], v1 = acc[mt][nt][h*2+1];
                if (EPI == 0) {
                    if (HASBIAS) { v0 += bias[nb]; v1 += bias[nb+1]; }
                    float* o = Cf + b*sC + (size_t)m*N + nb;
                    o[0] = v0; o[1] = v1;
                } else if (EPI == 1) {
                    const size_t base = (size_t)(b*sC) + (size_t)m*N + nb;
                    __nv_bfloat162 hi2, lo2;
                    split2(v0, v1, hi2, lo2);
                    *(__nv_bfloat162*)(Chi + base) = hi2;
                    *(__nv_bfloat162*)(Clo + base) = lo2;
                } else {  // EPI==3, Q/K route
                    const int which = nb >> 10;         // 0=Q, 1=K
                    const int nl = nb & 1023;
                    __nv_bfloat16* dh = which ? g_Khi : g_Qhi;
                    __nv_bfloat16* dl = which ? g_Klo : g_Qlo;
                    const size_t base = (size_t)m * DIM + nl;
                    __nv_bfloat162 hi2, lo2;
                    split2(v0, v1, hi2, lo2);
                    *(__nv_bfloat162*)(dh + base) = hi2;
                    *(__nv_bfloat162*)(dl + base) = lo2;
                }
            }
}

// ---------------------------------------------------------------------------
// fp32 -> (bf16 hi, bf16 lo) split, grid-strided, 4 elements per thread
// ---------------------------------------------------------------------------
__global__ void __launch_bounds__(256)
k_split(const float* __restrict__ src, __nv_bfloat16* __restrict__ hi,
        __nv_bfloat16* __restrict__ lo, int n)
{
    for (int i = (blockIdx.x * 256 + threadIdx.x) * 4; i < n; i += gridDim.x * 1024) {
        float4 v = *(const float4*)(src + i);
        __nv_bfloat162 h2a, l2a, h2b, l2b;
        split2(v.x, v.y, h2a, l2a);
        split2(v.z, v.w, h2b, l2b);
        __nv_bfloat162* ph = (__nv_bfloat162*)(hi + i);
        ph[0] = h2a; ph[1] = h2b;
        __nv_bfloat162* pl = (__nv_bfloat162*)(lo + i);
        pl[0] = l2a; pl[1] = l2b;
    }
}

// One launch: split Wq -> W[0], Wk -> W[1], Wo -> Wo buf (3 x DIM*DIM).
__global__ void __launch_bounds__(256)
k_split_w(const float* __restrict__ sq, const float* __restrict__ sk,
          const float* __restrict__ so,
          __nv_bfloat16* __restrict__ Whi, __nv_bfloat16* __restrict__ Wlo,
          __nv_bfloat16* __restrict__ Wohi, __nv_bfloat16* __restrict__ Wolo)
{
    const int i = (blockIdx.x * 256 + threadIdx.x) * 4;   // over 3*DIM*DIM
    const int w = i >> 20;                                // DIM*DIM = 1<<20
    const int off = i & (DIM*DIM - 1);
    const float* src = (w == 0) ? sq : (w == 1) ? sk : so;
    __nv_bfloat16* dh = (w == 2) ? Wohi : (Whi + (size_t)w * DIM*DIM);
    __nv_bfloat16* dl = (w == 2) ? Wolo : (Wlo + (size_t)w * DIM*DIM);
    float4 v = *(const float4*)(src + off);
    __nv_bfloat162 h2a, l2a, h2b, l2b;
    split2(v.x, v.y, h2a, l2a);
    split2(v.z, v.w, h2b, l2b);
    __nv_bfloat162* ph = (__nv_bfloat162*)(dh + off);
    ph[0] = h2a; ph[1] = h2b;
    __nv_bfloat162* pl = (__nv_bfloat162*)(dl + off);
    pl[0] = l2a; pl[1] = l2b;
}

// Transpose-split: Wvt[j][k] = split(Wv[k][j]). 32x32 smem tiles.
__global__ void __launch_bounds__(256)
k_split_t(const float* __restrict__ src, __nv_bfloat16* __restrict__ hi,
          __nv_bfloat16* __restrict__ lo)
{
    __shared__ float tile[32][33];
    const int k0 = blockIdx.y * 32, j0 = blockIdx.x * 32;
    const int tx = threadIdx.x & 31, ty = threadIdx.x >> 5;   // 32 x 8
    #pragma unroll
    for (int i = 0; i < 4; ++i)
        tile[ty + i*8][tx] = src[(size_t)(k0 + ty + i*8) * DIM + j0 + tx];
    __syncthreads();
    #pragma unroll
    for (int i = 0; i < 4; ++i) {
        const int j = ty + i*8;
        float v = tile[tx][j];
        __nv_bfloat16 h = __float2bfloat16(v);
        const size_t o = (size_t)(j0 + j) * DIM + k0 + tx;
        hi[o] = h;
        lo[o] = __float2bfloat16(v - __bfloat162float(h));
    }
}

// ---------------------------------------------------------------------------
// Causal row softmax, vectorized: float4 logit loads (row buffer is full S,
// masked beyond len), one exp pass, packed bf16x2 weight stores zero-padded
// to the next 128 boundary (PV K-bound). 256 threads, 4 contiguous elems x 2.
// ---------------------------------------------------------------------------
__global__ void __launch_bounds__(256)
k_softmax(const float* __restrict__ Pf, __nv_bfloat16* __restrict__ Phi,
          __nv_bfloat16* __restrict__ Plo, int S)
{
    const int b = blockIdx.z;
    const int row = blockIdx.x;
    const float* r = Pf + ((size_t)b * S + row) * S;
    __nv_bfloat16* oh = Phi + ((size_t)b * S + row) * S;
    __nv_bfloat16* ol = Plo + ((size_t)b * S + row) * S;
    const int len = row + 1;
    const int zend = ((row >> 7) + 1) << 7;   // next 128 boundary
    const int tid = threadIdx.x;

    __shared__ float red[8];

    float4 xv[2];
    float m = -INFINITY;
    #pragma unroll
    for (int j = 0; j < 2; ++j) {
        const int base = j * 1024 + tid * 4;
        xv[j] = *(const float4*)(r + base);   // always in-bounds (row len S)
        if (base + 0 < len) m = fmaxf(m, xv[j].x);
        if (base + 1 < len) m = fmaxf(m, xv[j].y);
        if (base + 2 < len) m = fmaxf(m, xv[j].z);
        if (base + 3 < len) m = fmaxf(m, xv[j].w);
    }
    #pragma unroll
    for (int o = 16; o; o >>= 1) m = fmaxf(m, __shfl_xor_sync(0xffffffffu, m, o));
    if ((tid & 31) == 0) red[tid >> 5] = m;
    __syncthreads();
    float mm = -INFINITY;
    #pragma unroll
    for (int i = 0; i < 8; ++i) mm = fmaxf(mm, red[i]);
    __syncthreads();

    float4 ev[2];
    float s = 0.f;
    #pragma unroll
    for (int j = 0; j < 2; ++j) {
        const int base = j * 1024 + tid * 4;
        ev[j].x = (base + 0 < len) ? __expf(xv[j].x - mm) : 0.f;
        ev[j].y = (base + 1 < len) ? __expf(xv[j].y - mm) : 0.f;
        ev[j].z = (base + 2 < len) ? __expf(xv[j].z - mm) : 0.f;
        ev[j].w = (base + 3 < len) ? __expf(xv[j].w - mm) : 0.f;
        s += ev[j].x + ev[j].y + ev[j].z + ev[j].w;
    }
    #pragma unroll
    for (int o = 16; o; o >>= 1) s += __shfl_xor_sync(0xffffffffu, s, o);
    if ((tid & 31) == 0) red[tid >> 5] = s;
    __syncthreads();
    float ss = 0.f;
    #pragma unroll
    for (int i = 0; i < 8; ++i) ss += red[i];
    const float inv = 1.f / ss;

    #pragma unroll
    for (int j = 0; j < 2; ++j) {
        const int base = j * 1024 + tid * 4;
        if (base >= zend) continue;
        float p0 = ev[j].x * inv, p1 = ev[j].y * inv;
        float p2 = ev[j].z * inv, p3 = ev[j].w * inv;
        __nv_bfloat162 h2a, l2a, h2b, l2b;
        split2(p0, p1, h2a, l2a);
        split2(p2, p3, h2b, l2b);
        __nv_bfloat162* ph = (__nv_bfloat162*)(oh + base);
        ph[0] = h2a; ph[1] = h2b;
        __nv_bfloat162* pl = (__nv_bfloat162*)(ol + base);
        pl[0] = l2a; pl[1] = l2b;
    }
}

// ---------------------------------------------------------------------------
extern "C" void kernel_launch(void* const* d_in, const int* in_sizes, int n_in,
                              void* d_out, int out_size)
{
    const float* x  = (const float*)d_in[0];
    const float* WQ = (const float*)d_in[1];
    const float* WK = (const float*)d_in[2];
    const float* WV = (const float*)d_in[3];
    const float* WO = (const float*)d_in[4];
    const float* bO = (const float*)d_in[5];
    float* out = (float*)d_out;

    __nv_bfloat16 *xhi, *xlo, *Whi, *Wlo, *Wohi, *Wolo, *Wvthi, *Wvtlo;
    __nv_bfloat16 *Qhi, *Qlo, *Khi, *Klo, *Vthi, *Vtlo, *Phi, *Plo;
    float* Pf;
    cudaGetSymbolAddress((void**)&xhi, g_xhi);     cudaGetSymbolAddress((void**)&xlo, g_xlo);
    cudaGetSymbolAddress((void**)&Whi, g_Whi);     cudaGetSymbolAddress((void**)&Wlo, g_Wlo);
    cudaGetSymbolAddress((void**)&Wohi, g_Wohi);   cudaGetSymbolAddress((void**)&Wolo, g_Wolo);
    cudaGetSymbolAddress((void**)&Wvthi, g_Wvthi); cudaGetSymbolAddress((void**)&Wvtlo, g_Wvtlo);
    cudaGetSymbolAddress((void**)&Qhi, g_Qhi);     cudaGetSymbolAddress((void**)&Qlo, g_Qlo);
    cudaGetSymbolAddress((void**)&Khi, g_Khi);     cudaGetSymbolAddress((void**)&Klo, g_Klo);
    cudaGetSymbolAddress((void**)&Vthi, g_Vthi);   cudaGetSymbolAddress((void**)&Vtlo, g_Vtlo);
    cudaGetSymbolAddress((void**)&Phi, g_Phi);     cudaGetSymbolAddress((void**)&Plo, g_Plo);
    cudaGetSymbolAddress((void**)&Pf, g_Pf);

    cudaFuncSetAttribute(k_tc<1,false,false,false,false,8>, cudaFuncAttributeMaxDynamicSharedMemorySize, SMEM_BYTES);
    cudaFuncSetAttribute(k_tc<3,false,false,false,false,4>, cudaFuncAttributeMaxDynamicSharedMemorySize, SMEM_BYTES);
    cudaFuncSetAttribute(k_tc<0,true ,false,false,false,8>, cudaFuncAttributeMaxDynamicSharedMemorySize, SMEM_BYTES);
    cudaFuncSetAttribute(k_tc<0,false,true ,true ,true ,8>, cudaFuncAttributeMaxDynamicSharedMemorySize, SMEM_BYTES);

    // 1. Splits: x; Wq/Wk/Wo; Wv transposed (for the Wc GEMM's B operand)
    k_split<<<(MROWS*DIM/4 + 255)/256, 256>>>(x, xhi, xlo, MROWS*DIM);
    k_split_w<<<(3*DIM*DIM/4 + 255)/256, 256>>>(WQ, WK, WO, Whi, Wlo, Wohi, Wolo);
    k_split_t<<<dim3(DIM/32, DIM/32), 256>>>(WV, Wvthi, Wvtlo);

    // 2. Wc = Wo @ Wv  (= Wo @ Wvt^T), written hi/lo into stacked V slot
    k_tc<1,false,false,false,false,8><<<dim3(DIM/128, DIM/128, 1), 128, SMEM_BYTES>>>(
        Wohi, Wolo, Wvthi, Wvtlo, nullptr, Whi + 2*(size_t)DIM*DIM, Wlo + 2*(size_t)DIM*DIM,
        nullptr, DIM, DIM, 0, 0, 0);

    // 3. Merged QK+VW projection (config A): x @ [Wq; Wk; Wc]^T, routed epilogue
    //    (V slot produces VW = x@Wc^T, stored transposed [B, D, S])
    k_tc<3,false,false,false,false,4><<<dim3(3*DIM/128, MROWS/128, 1), 256, SMEM_BYTES>>>(
        xhi, xlo, Whi, Wlo, nullptr, nullptr, nullptr, nullptr,
        3*DIM, DIM, 0, 0, 0);

    // 4. Causal scores (config B), exact triangular grid, longest-first
    k_tc<0,true,false,false,false,8><<<dim3(136, 1, BATCH), 128, SMEM_BYTES>>>(
        Qhi, Qlo, Khi, Klo, Pf, nullptr, nullptr, nullptr,
        SEQ, DIM, (long long)SEQ*DIM, (long long)SEQ*DIM, (long long)SEQ*SEQ);

    // 5. Softmax (vectorized float4 loads, packed bf16x2 stores)
    k_softmax<<<dim3(SEQ, 1, BATCH), 256>>>(Pf, Phi, Plo, SEQ);

    // 6. Final: out = P @ VW + b  (config B, fp32+bias epilogue, K-bounded,
    //    longest blocks first) — output projection is folded into VW.
    k_tc<0,false,true,true,true,8><<<dim3(DIM/128, SEQ/128, BATCH), 128, SMEM_BYTES>>>(
        Phi, Plo, Vthi, Vtlo, out, nullptr, nullptr, bO,
        DIM, SEQ, (long long)SEQ*SEQ, (long long)DIM*SEQ, (long long)SEQ*DIM);
}

// round 16
// speedup vs baseline: 1.1535x; 1.0005x over previous
#include <cuda_runtime.h>
#include <cuda_bf16.h>
#include <math.h>
#include <stdint.h>

#define BATCH 4
#define SEQ   2048
#define DIM   1024
#define MROWS (BATCH*SEQ)   // 8192

// ---------------------------------------------------------------------------
// Scratch (__device__ globals; runtime allocation is forbidden)
// ---------------------------------------------------------------------------
__device__ __nv_bfloat16 g_xhi[MROWS*DIM],  g_xlo[MROWS*DIM];
__device__ __nv_bfloat16 g_Whi[3*DIM*DIM],  g_Wlo[3*DIM*DIM];   // stacked Wq,Wk,Wc
__device__ __nv_bfloat16 g_Wohi[DIM*DIM],   g_Wolo[DIM*DIM];    // Wo split
__device__ __nv_bfloat16 g_Wvthi[DIM*DIM],  g_Wvtlo[DIM*DIM];   // Wv^T split
__device__ __nv_bfloat16 g_Qhi[MROWS*DIM],  g_Qlo[MROWS*DIM];
__device__ __nv_bfloat16 g_Khi[MROWS*DIM],  g_Klo[MROWS*DIM];
__device__ __nv_bfloat16 g_Vthi[MROWS*DIM], g_Vtlo[MROWS*DIM];  // VW^T: [B, D, S]
__device__ float         g_Pf[(size_t)BATCH*SEQ*SEQ];
__device__ __nv_bfloat16 g_Phi[(size_t)BATCH*SEQ*SEQ], g_Plo[(size_t)BATCH*SEQ*SEQ];

// ---------------------------------------------------------------------------
// Helpers
// ---------------------------------------------------------------------------
__device__ __forceinline__ uint32_t smem_u32(const void* p) {
    uint32_t a;
    asm("{ .reg .u64 t; cvta.to.shared.u64 t, %1; cvt.u32.u64 %0, t; }" : "=r"(a) : "l"(p));
    return a;
}

// XOR swizzle for 64B-row tiles (8 rows x 64B atom): conflict-free ldmatrix
#define SWZ64(off) ((uint32_t)(off) ^ (((uint32_t)(off) >> 3) & 0x30))

#define CP16(dst, src) \
    asm volatile("cp.async.cg.shared.global [%0], [%1], 16;" :: "r"(dst), "l"(src))
#define CPCOMMIT() asm volatile("cp.async.commit_group;" ::: "memory")
#define CPWAIT(n)  asm volatile("cp.async.wait_group %0;" :: "n"(n) : "memory")

__device__ __forceinline__ void ldm4(uint32_t* r, uint32_t addr) {
    asm volatile("ldmatrix.sync.aligned.m8n8.x4.shared.b16 {%0,%1,%2,%3}, [%4];"
        : "=r"(r[0]), "=r"(r[1]), "=r"(r[2]), "=r"(r[3]) : "r"(addr));
}

__device__ __forceinline__ void mma16816(float* c, const uint32_t* a, const uint32_t* b) {
    asm volatile("mma.sync.aligned.m16n8k16.row.col.f32.bf16.bf16.f32 "
        "{%0,%1,%2,%3}, {%4,%5,%6,%7}, {%8,%9}, {%0,%1,%2,%3};"
        : "+f"(c[0]), "+f"(c[1]), "+f"(c[2]), "+f"(c[3])
        : "r"(a[0]), "r"(a[1]), "r"(a[2]), "r"(a[3]), "r"(b[0]), "r"(b[1]));
}

// pack two fp32 into bf16x2 + residual bf16x2
__device__ __forceinline__ void split2(float v0, float v1,
                                       __nv_bfloat162& hi2, __nv_bfloat162& lo2) {
    __nv_bfloat16 h0 = __float2bfloat16(v0), h1 = __float2bfloat16(v1);
    hi2 = __nv_bfloat162(h0, h1);
    lo2 = __nv_bfloat162(__float2bfloat16(v0 - __bfloat162float(h0)),
                         __float2bfloat16(v1 - __bfloat162float(h1)));
}

// ---------------------------------------------------------------------------
// Tensor-core GEMM: C(128x128 tiles) = A * B^T, 3-MMA bf16 split precision.
// NTN = n-tiles (8 cols each) per warp:
//   NTN=4: 256 thr, 8 warps 2x4, warp 64x32  (epilogue-heavy / low-occupancy)
//   NTN=8: 128 thr, 4 warps 2x2, warp 64x64  (mainloop-bound, big grids)
// 2 CTAs/SM in both configs.
// EPI: 0 = fp32 out (+bias), 1 = bf16 hi/lo out, 3 = QKV-routed (Q/K direct,
//      V-slot transposed via smem staging). hi/lo stores are packed bf16x2.
// CAUSAL: exact triangular grid decode, longest-first
// ---------------------------------------------------------------------------
#define STAGE_BYTES 32768
#define OFF_AHI 0
#define OFF_ALO 8192
#define OFF_BHI 16384
#define OFF_BLO 24576
#define SMEM_BYTES 65536     // 2 stages
#define TPITCH 136           // transpose staging pitch (bf16 elements)

template<int EPI, bool CAUSAL, bool KBOUND, bool HASBIAS, bool REV, int NTN>
__global__ void __launch_bounds__((NTN==4 ? 256 : 128), 2)
k_tc(const __nv_bfloat16* __restrict__ Ahi, const __nv_bfloat16* __restrict__ Alo,
     const __nv_bfloat16* __restrict__ Bhi, const __nv_bfloat16* __restrict__ Blo,
     float* __restrict__ Cf, __nv_bfloat16* __restrict__ Chi, __nv_bfloat16* __restrict__ Clo,
     const float* __restrict__ bias,
     int N, int Kdim, long long sA, long long sB, long long sC)
{
    constexpr int NT = (NTN==4 ? 256 : 128);   // threads
    constexpr int WNOFF = NTN * 8;             // warp n-span
    int m0, n0;
    if (CAUSAL) {
        // longest-first: reverse the triangular index
        const int tix = (int)gridDim.x - 1 - (int)blockIdx.x;
        int mb = (int)((sqrtf(8.f * tix + 1.f) - 1.f) * 0.5f + 1e-4f);
        while ((mb + 1) * (mb + 2) / 2 <= tix) ++mb;
        while (mb * (mb + 1) / 2 > tix) --mb;
        const int nb = tix - mb * (mb + 1) / 2;
        m0 = mb * 128;
        n0 = nb * 128;
    } else {
        const int by = REV ? (gridDim.y - 1 - blockIdx.y) : blockIdx.y;
        m0 = by * 128;
        n0 = blockIdx.x * 128;
    }
    const long long b = blockIdx.z;
    Ahi += b * sA; Alo += b * sA;
    Bhi += b * sB; Blo += b * sB;

    extern __shared__ char smem[];
    const uint32_t sb = smem_u32(smem);
    const int tid = threadIdx.x, lane = tid & 31, wid = tid >> 5;
    const int wm = wid & 1, wn = wid >> 1;     // warp tile 64(m) x WNOFF(n)

    const int kend = KBOUND ? (m0 + 128) : Kdim;
    const int nchunk = kend >> 5;              // BK = 32

    float acc[4][NTN][4];
    #pragma unroll
    for (int i = 0; i < 4; ++i)
        #pragma unroll
        for (int j = 0; j < NTN; ++j)
            #pragma unroll
            for (int r = 0; r < 4; ++r) acc[i][j][r] = 0.f;

    // stage loader: 4 tiles of 128 rows x 64B, SWZ64 layout, cp.async 16B
    auto load_stage = [&](int c, int s) {
        const int k0 = c << 5;
        const uint32_t sbase = sb + s * STAGE_BYTES;
        #pragma unroll
        for (int h = 0; h < 512/NT; ++h) {
            const int idx = tid + h * NT;      // 0..511
            const int row = idx >> 2, ch = idx & 3;
            const uint32_t so = SWZ64(row * 64 + ch * 16);
            const size_t gA = (size_t)(m0 + row) * Kdim + k0 + ch * 8;
            const size_t gB = (size_t)(n0 + row) * Kdim + k0 + ch * 8;
            CP16(sbase + OFF_AHI + so, Ahi + gA);
            CP16(sbase + OFF_ALO + so, Alo + gA);
            CP16(sbase + OFF_BHI + so, Bhi + gB);
            CP16(sbase + OFF_BLO + so, Blo + gB);
        }
    };

    load_stage(0, 0); CPCOMMIT();

    // Single-barrier pipeline: wait(c) -> barrier -> issue(c+1) -> consume(c).
    for (int c = 0; c < nchunk; ++c) {
        CPWAIT(0);
        __syncthreads();
        if (c + 1 < nchunk) { load_stage(c + 1, (c + 1) & 1); CPCOMMIT(); }

        const uint32_t sA = sb + (c & 1) * STAGE_BYTES;
        #pragma unroll
        for (int kk = 0; kk < 32; kk += 16) {
            // B fragments: NTN nt tiles (hi+lo)
            uint32_t bhi[NTN][2], blo[NTN][2];
            const int brow  = (lane & 7) + ((lane & 16) ? 8 : 0);
            const int bkoff = (lane & 8) ? 8 : 0;
            #pragma unroll
            for (int np = 0; np < NTN/2; ++np) {
                const uint32_t off = SWZ64((wn*WNOFF + np*16 + brow) * 64 + (kk + bkoff) * 2);
                uint32_t t4[4];
                ldm4(t4, sA + OFF_BHI + off);
                bhi[np*2][0] = t4[0]; bhi[np*2][1] = t4[1];
                bhi[np*2+1][0] = t4[2]; bhi[np*2+1][1] = t4[3];
                ldm4(t4, sA + OFF_BLO + off);
                blo[np*2][0] = t4[0]; blo[np*2][1] = t4[1];
                blo[np*2+1][0] = t4[2]; blo[np*2+1][1] = t4[3];
            }
            // A fragments: 4 mt tiles, hi and lo in separate regs
            const int arow  = lane & 15;
            const int akoff = (lane >> 4) << 3;
            uint32_t ahi[4][4], alo[4][4];
            #pragma unroll
            for (int mt = 0; mt < 4; ++mt) {
                const uint32_t off = SWZ64((wm*64 + mt*16 + arow) * 64 + (kk + akoff) * 2);
                ldm4(ahi[mt], sA + OFF_AHI + off);
                ldm4(alo[mt], sA + OFF_ALO + off);
            }
            // pass 1: hi*hi
            #pragma unroll
            for (int mt = 0; mt < 4; ++mt)
                #pragma unroll
                for (int nt = 0; nt < NTN; ++nt)
                    mma16816(acc[mt][nt], ahi[mt], bhi[nt]);
            // pass 2: hi*lo
            #pragma unroll
            for (int mt = 0; mt < 4; ++mt)
                #pragma unroll
                for (int nt = 0; nt < NTN; ++nt)
                    mma16816(acc[mt][nt], ahi[mt], blo[nt]);
            // pass 3: lo*hi
            #pragma unroll
            for (int mt = 0; mt < 4; ++mt)
                #pragma unroll
                for (int nt = 0; nt < NTN; ++nt)
                    mma16816(acc[mt][nt], alo[mt], bhi[nt]);
        }
    }

    // Epilogue. C frag: (c0,c1) row g cols t*2,t*2+1; (c2,c3) row g+8.
    const int g = lane >> 2, t = lane & 3;
    const bool vpath = (EPI == 3) && (n0 >= 2*DIM);
    if (vpath) {
        // V-slot (x @ Wc^T): smem-staged transpose [n][m], coalesced stores.
        __syncthreads();   // laggards may still be reading stage smem
        __nv_bfloat16* tsm = (__nv_bfloat16*)smem;
        const int bb = m0 >> 11, sbase_s = m0 & 2047;
        const int nvl0 = n0 - 2*DIM;
        #pragma unroll
        for (int comp = 0; comp < 2; ++comp) {
            #pragma unroll
            for (int mt = 0; mt < 4; ++mt)
                #pragma unroll
                for (int nt = 0; nt < NTN; ++nt)
                    #pragma unroll
                    for (int h = 0; h < 2; ++h) {
                        const int ml = wm*64 + mt*16 + g + h*8;
                        const int nl = wn*WNOFF + nt*8 + t*2;
                        float v0 = acc[mt][nt][h*2], v1 = acc[mt][nt][h*2+1];
                        __nv_bfloat162 hi2, lo2;
                        split2(v0, v1, hi2, lo2);
                        __nv_bfloat162 o2 = (comp == 0) ? hi2 : lo2;
                        tsm[(size_t)nl * TPITCH + ml]     = o2.x;
                        tsm[(size_t)(nl+1) * TPITCH + ml] = o2.y;
                    }
            __syncthreads();
            __nv_bfloat16* dst = (comp == 0) ? g_Vthi : g_Vtlo;
            // NT threads cover 128 rows x (NT/128) col-chunks
            constexpr int CHW = 16384 / NT;    // bf16 per thread (64 or 128)
            const int nl = tid / (NT/128), mh = (tid % (NT/128)) * CHW;
            const __nv_bfloat16* srow = tsm + (size_t)nl * TPITCH + mh;
            __nv_bfloat16* drow = dst + ((size_t)bb * DIM + (nvl0 + nl)) * SEQ + sbase_s + mh;
            #pragma unroll
            for (int q = 0; q < CHW/8; ++q)
                *(uint4*)(drow + q*8) = *(const uint4*)(srow + q*8);
            __syncthreads();
        }
        return;
    }
    #pragma unroll
    for (int mt = 0; mt < 4; ++mt)
        #pragma unroll
        for (int nt = 0; nt < NTN; ++nt)
            #pragma unroll
            for (int h = 0; h < 2; ++h) {
                const int m  = m0 + wm*64 + mt*16 + g + h*8;
                const int nb = n0 + wn*WNOFF + nt*8 + t*2;
                float v0 = acc[mt][nt][h*2], v1 = acc[mt][nt][h*2+1];
                if (EPI == 0) {
                    if (HASBIAS) { v0 += bias[nb]; v1 += bias[nb+1]; }
                    float* o = Cf + b*sC + (size_t)m*N + nb;
                    o[0] = v0; o[1] = v1;
                } else if (EPI == 1) {
                    const size_t base = (size_t)(b*sC) + (size_t)m*N + nb;
                    __nv_bfloat162 hi2, lo2;
                    split2(v0, v1, hi2, lo2);
                    *(__nv_bfloat162*)(Chi + base) = hi2;
                    *(__nv_bfloat162*)(Clo + base) = lo2;
                } else {  // EPI==3, Q/K route
                    const int which = nb >> 10;         // 0=Q, 1=K
                    const int nl = nb & 1023;
                    __nv_bfloat16* dh = which ? g_Khi : g_Qhi;
                    __nv_bfloat16* dl = which ? g_Klo : g_Qlo;
                    const size_t base = (size_t)m * DIM + nl;
                    __nv_bfloat162 hi2, lo2;
                    split2(v0, v1, hi2, lo2);
                    *(__nv_bfloat162*)(dh + base) = hi2;
                    *(__nv_bfloat162*)(dl + base) = lo2;
                }
            }
}

// ---------------------------------------------------------------------------
// fp32 -> (bf16 hi, bf16 lo) split, grid-strided, 4 elements per thread
// ---------------------------------------------------------------------------
__global__ void __launch_bounds__(256)
k_split(const float* __restrict__ src, __nv_bfloat16* __restrict__ hi,
        __nv_bfloat16* __restrict__ lo, int n)
{
    for (int i = (blockIdx.x * 256 + threadIdx.x) * 4; i < n; i += gridDim.x * 1024) {
        float4 v = *(const float4*)(src + i);
        __nv_bfloat162 h2a, l2a, h2b, l2b;
        split2(v.x, v.y, h2a, l2a);
        split2(v.z, v.w, h2b, l2b);
        __nv_bfloat162* ph = (__nv_bfloat162*)(hi + i);
        ph[0] = h2a; ph[1] = h2b;
        __nv_bfloat162* pl = (__nv_bfloat162*)(lo + i);
        pl[0] = l2a; pl[1] = l2b;
    }
}

// One launch: split Wq -> W[0], Wk -> W[1], Wo -> Wo buf (3 x DIM*DIM).
__global__ void __launch_bounds__(256)
k_split_w(const float* __restrict__ sq, const float* __restrict__ sk,
          const float* __restrict__ so,
          __nv_bfloat16* __restrict__ Whi, __nv_bfloat16* __restrict__ Wlo,
          __nv_bfloat16* __restrict__ Wohi, __nv_bfloat16* __restrict__ Wolo)
{
    const int i = (blockIdx.x * 256 + threadIdx.x) * 4;   // over 3*DIM*DIM
    const int w = i >> 20;                                // DIM*DIM = 1<<20
    const int off = i & (DIM*DIM - 1);
    const float* src = (w == 0) ? sq : (w == 1) ? sk : so;
    __nv_bfloat16* dh = (w == 2) ? Wohi : (Whi + (size_t)w * DIM*DIM);
    __nv_bfloat16* dl = (w == 2) ? Wolo : (Wlo + (size_t)w * DIM*DIM);
    float4 v = *(const float4*)(src + off);
    __nv_bfloat162 h2a, l2a, h2b, l2b;
    split2(v.x, v.y, h2a, l2a);
    split2(v.z, v.w, h2b, l2b);
    __nv_bfloat162* ph = (__nv_bfloat162*)(dh + off);
    ph[0] = h2a; ph[1] = h2b;
    __nv_bfloat162* pl = (__nv_bfloat162*)(dl + off);
    pl[0] = l2a; pl[1] = l2b;
}

// Transpose-split: Wvt[j][k] = split(Wv[k][j]). 32x32 smem tiles.
__global__ void __launch_bounds__(256)
k_split_t(const float* __restrict__ src, __nv_bfloat16* __restrict__ hi,
          __nv_bfloat16* __restrict__ lo)
{
    __shared__ float tile[32][33];
    const int k0 = blockIdx.y * 32, j0 = blockIdx.x * 32;
    const int tx = threadIdx.x & 31, ty = threadIdx.x >> 5;   // 32 x 8
    #pragma unroll
    for (int i = 0; i < 4; ++i)
        tile[ty + i*8][tx] = src[(size_t)(k0 + ty + i*8) * DIM + j0 + tx];
    __syncthreads();
    #pragma unroll
    for (int i = 0; i < 4; ++i) {
        const int j = ty + i*8;
        float v = tile[tx][j];
        __nv_bfloat16 h = __float2bfloat16(v);
        const size_t o = (size_t)(j0 + j) * DIM + k0 + tx;
        hi[o] = h;
        lo[o] = __float2bfloat16(v - __bfloat162float(h));
    }
}

// ---------------------------------------------------------------------------
// Causal row softmax, vectorized: float4 logit loads (row buffer is full S,
// masked beyond len), one exp pass, packed bf16x2 weight stores zero-padded
// to the next 128 boundary (PV K-bound). 256 threads, 4 contiguous elems x 2.
// ---------------------------------------------------------------------------
__global__ void __launch_bounds__(256)
k_softmax(const float* __restrict__ Pf, __nv_bfloat16* __restrict__ Phi,
          __nv_bfloat16* __restrict__ Plo, int S)
{
    const int b = blockIdx.z;
    const int row = blockIdx.x;
    const float* r = Pf + ((size_t)b * S + row) * S;
    __nv_bfloat16* oh = Phi + ((size_t)b * S + row) * S;
    __nv_bfloat16* ol = Plo + ((size_t)b * S + row) * S;
    const int len = row + 1;
    const int zend = ((row >> 7) + 1) << 7;   // next 128 boundary
    const int tid = threadIdx.x;

    __shared__ float red[8];

    float4 xv[2];
    float m = -INFINITY;
    #pragma unroll
    for (int j = 0; j < 2; ++j) {
        const int base = j * 1024 + tid * 4;
        xv[j] = *(const float4*)(r + base);   // always in-bounds (row len S)
        if (base + 0 < len) m = fmaxf(m, xv[j].x);
        if (base + 1 < len) m = fmaxf(m, xv[j].y);
        if (base + 2 < len) m = fmaxf(m, xv[j].z);
        if (base + 3 < len) m = fmaxf(m, xv[j].w);
    }
    #pragma unroll
    for (int o = 16; o; o >>= 1) m = fmaxf(m, __shfl_xor_sync(0xffffffffu, m, o));
    if ((tid & 31) == 0) red[tid >> 5] = m;
    __syncthreads();
    float mm = -INFINITY;
    #pragma unroll
    for (int i = 0; i < 8; ++i) mm = fmaxf(mm, red[i]);
    __syncthreads();

    float4 ev[2];
    float s = 0.f;
    #pragma unroll
    for (int j = 0; j < 2; ++j) {
        const int base = j * 1024 + tid * 4;
        ev[j].x = (base + 0 < len) ? __expf(xv[j].x - mm) : 0.f;
        ev[j].y = (base + 1 < len) ? __expf(xv[j].y - mm) : 0.f;
        ev[j].z = (base + 2 < len) ? __expf(xv[j].z - mm) : 0.f;
        ev[j].w = (base + 3 < len) ? __expf(xv[j].w - mm) : 0.f;
        s += ev[j].x + ev[j].y + ev[j].z + ev[j].w;
    }
    #pragma unroll
    for (int o = 16; o; o >>= 1) s += __shfl_xor_sync(0xffffffffu, s, o);
    if ((tid & 31) == 0) red[tid >> 5] = s;
    __syncthreads();
    float ss = 0.f;
    #pragma unroll
    for (int i = 0; i < 8; ++i) ss += red[i];
    const float inv = 1.f / ss;

    #pragma unroll
    for (int j = 0; j < 2; ++j) {
        const int base = j * 1024 + tid * 4;
        if (base >= zend) continue;
        float p0 = ev[j].x * inv, p1 = ev[j].y * inv;
        float p2 = ev[j].z * inv, p3 = ev[j].w * inv;
        __nv_bfloat162 h2a, l2a, h2b, l2b;
        split2(p0, p1, h2a, l2a);
        split2(p2, p3, h2b, l2b);
        __nv_bfloat162* ph = (__nv_bfloat162*)(oh + base);
        ph[0] = h2a; ph[1] = h2b;
        __nv_bfloat162* pl = (__nv_bfloat162*)(ol + base);
        pl[0] = l2a; pl[1] = l2b;
    }
}

// ---------------------------------------------------------------------------
extern "C" void kernel_launch(void* const* d_in, const int* in_sizes, int n_in,
                              void* d_out, int out_size)
{
    const float* x  = (const float*)d_in[0];
    const float* WQ = (const float*)d_in[1];
    const float* WK = (const float*)d_in[2];
    const float* WV = (const float*)d_in[3];
    const float* WO = (const float*)d_in[4];
    const float* bO = (const float*)d_in[5];
    float* out = (float*)d_out;

    __nv_bfloat16 *xhi, *xlo, *Whi, *Wlo, *Wohi, *Wolo, *Wvthi, *Wvtlo;
    __nv_bfloat16 *Qhi, *Qlo, *Khi, *Klo, *Vthi, *Vtlo, *Phi, *Plo;
    float* Pf;
    cudaGetSymbolAddress((void**)&xhi, g_xhi);     cudaGetSymbolAddress((void**)&xlo, g_xlo);
    cudaGetSymbolAddress((void**)&Whi, g_Whi);     cudaGetSymbolAddress((void**)&Wlo, g_Wlo);
    cudaGetSymbolAddress((void**)&Wohi, g_Wohi);   cudaGetSymbolAddress((void**)&Wolo, g_Wolo);
    cudaGetSymbolAddress((void**)&Wvthi, g_Wvthi); cudaGetSymbolAddress((void**)&Wvtlo, g_Wvtlo);
    cudaGetSymbolAddress((void**)&Qhi, g_Qhi);     cudaGetSymbolAddress((void**)&Qlo, g_Qlo);
    cudaGetSymbolAddress((void**)&Khi, g_Khi);     cudaGetSymbolAddress((void**)&Klo, g_Klo);
    cudaGetSymbolAddress((void**)&Vthi, g_Vthi);   cudaGetSymbolAddress((void**)&Vtlo, g_Vtlo);
    cudaGetSymbolAddress((void**)&Phi, g_Phi);     cudaGetSymbolAddress((void**)&Plo, g_Plo);
    cudaGetSymbolAddress((void**)&Pf, g_Pf);

    cudaFuncSetAttribute(k_tc<1,false,false,false,false,4>, cudaFuncAttributeMaxDynamicSharedMemorySize, SMEM_BYTES);
    cudaFuncSetAttribute(k_tc<3,false,false,false,false,4>, cudaFuncAttributeMaxDynamicSharedMemorySize, SMEM_BYTES);
    cudaFuncSetAttribute(k_tc<0,true ,false,false,false,8>, cudaFuncAttributeMaxDynamicSharedMemorySize, SMEM_BYTES);
    cudaFuncSetAttribute(k_tc<0,false,true ,true ,true ,8>, cudaFuncAttributeMaxDynamicSharedMemorySize, SMEM_BYTES);

    // 1. Splits: x; Wq/Wk/Wo; Wv transposed (for the Wc GEMM's B operand)
    k_split<<<(MROWS*DIM/4 + 255)/256, 256>>>(x, xhi, xlo, MROWS*DIM);
    k_split_w<<<(3*DIM*DIM/4 + 255)/256, 256>>>(WQ, WK, WO, Whi, Wlo, Wohi, Wolo);
    k_split_t<<<dim3(DIM/32, DIM/32), 256>>>(WV, Wvthi, Wvtlo);

    // 2. Wc = Wo @ Wv  (= Wo @ Wvt^T), written hi/lo into stacked V slot.
    //    Config A (256 thr): 64-CTA grid is latency-bound, needs warps.
    k_tc<1,false,false,false,false,4><<<dim3(DIM/128, DIM/128, 1), 256, SMEM_BYTES>>>(
        Wohi, Wolo, Wvthi, Wvtlo, nullptr, Whi + 2*(size_t)DIM*DIM, Wlo + 2*(size_t)DIM*DIM,
        nullptr, DIM, DIM, 0, 0, 0);

    // 3. Merged QK+VW projection (config A): x @ [Wq; Wk; Wc]^T, routed epilogue
    //    (V slot produces VW = x@Wc^T, stored transposed [B, D, S])
    k_tc<3,false,false,false,false,4><<<dim3(3*DIM/128, MROWS/128, 1), 256, SMEM_BYTES>>>(
        xhi, xlo, Whi, Wlo, nullptr, nullptr, nullptr, nullptr,
        3*DIM, DIM, 0, 0, 0);

    // 4. Causal scores (config B), exact triangular grid, longest-first
    k_tc<0,true,false,false,false,8><<<dim3(136, 1, BATCH), 128, SMEM_BYTES>>>(
        Qhi, Qlo, Khi, Klo, Pf, nullptr, nullptr, nullptr,
        SEQ, DIM, (long long)SEQ*DIM, (long long)SEQ*DIM, (long long)SEQ*SEQ);

    // 5. Softmax (vectorized float4 loads, packed bf16x2 stores)
    k_softmax<<<dim3(SEQ, 1, BATCH), 256>>>(Pf, Phi, Plo, SEQ);

    // 6. Final: out = P @ VW + b  (config B, fp32+bias epilogue, K-bounded,
    //    longest blocks first) — output projection is folded into VW.
    k_tc<0,false,true,true,true,8><<<dim3(DIM/128, SEQ/128, BATCH), 128, SMEM_BYTES>>>(
        Phi, Plo, Vthi, Vtlo, out, nullptr, nullptr, bO,
        DIM, SEQ, (long long)SEQ*SEQ, (long long)DIM*SEQ, (long long)SEQ*DIM);
}

// round 17
// speedup vs baseline: 1.1778x; 1.0210x over previous
#include <cuda_runtime.h>
#include <cuda_bf16.h>
#include <math.h>
#include <stdint.h>

#define BATCH 4
#define SEQ   2048
#define DIM   1024
#define MROWS (BATCH*SEQ)   // 8192

// ---------------------------------------------------------------------------
// Scratch (__device__ globals; runtime allocation is forbidden)
// ---------------------------------------------------------------------------
__device__ __nv_bfloat16 g_xhi[MROWS*DIM],  g_xlo[MROWS*DIM];
__device__ __nv_bfloat16 g_Whi[3*DIM*DIM],  g_Wlo[3*DIM*DIM];   // stacked Wq,Wk,Wc
__device__ __nv_bfloat16 g_Wohi[DIM*DIM],   g_Wolo[DIM*DIM];    // Wo split
__device__ __nv_bfloat16 g_Wvthi[DIM*DIM],  g_Wvtlo[DIM*DIM];   // Wv^T split
__device__ __nv_bfloat16 g_Qhi[MROWS*DIM],  g_Qlo[MROWS*DIM];
__device__ __nv_bfloat16 g_Khi[MROWS*DIM],  g_Klo[MROWS*DIM];
__device__ __nv_bfloat16 g_Vthi[MROWS*DIM], g_Vtlo[MROWS*DIM];  // VW^T: [B, D, S]
__device__ float         g_Pf[(size_t)BATCH*SEQ*SEQ];           // also Wc partials
__device__ __nv_bfloat16 g_Phi[(size_t)BATCH*SEQ*SEQ], g_Plo[(size_t)BATCH*SEQ*SEQ];

// ---------------------------------------------------------------------------
// Helpers
// ---------------------------------------------------------------------------
__device__ __forceinline__ uint32_t smem_u32(const void* p) {
    uint32_t a;
    asm("{ .reg .u64 t; cvta.to.shared.u64 t, %1; cvt.u32.u64 %0, t; }" : "=r"(a) : "l"(p));
    return a;
}

// XOR swizzle for 64B-row tiles (8 rows x 64B atom): conflict-free ldmatrix
#define SWZ64(off) ((uint32_t)(off) ^ (((uint32_t)(off) >> 3) & 0x30))

#define CP16(dst, src) \
    asm volatile("cp.async.cg.shared.global [%0], [%1], 16;" :: "r"(dst), "l"(src))
#define CPCOMMIT() asm volatile("cp.async.commit_group;" ::: "memory")
#define CPWAIT(n)  asm volatile("cp.async.wait_group %0;" :: "n"(n) : "memory")

__device__ __forceinline__ void ldm4(uint32_t* r, uint32_t addr) {
    asm volatile("ldmatrix.sync.aligned.m8n8.x4.shared.b16 {%0,%1,%2,%3}, [%4];"
        : "=r"(r[0]), "=r"(r[1]), "=r"(r[2]), "=r"(r[3]) : "r"(addr));
}

__device__ __forceinline__ void mma16816(float* c, const uint32_t* a, const uint32_t* b) {
    asm volatile("mma.sync.aligned.m16n8k16.row.col.f32.bf16.bf16.f32 "
        "{%0,%1,%2,%3}, {%4,%5,%6,%7}, {%8,%9}, {%0,%1,%2,%3};"
        : "+f"(c[0]), "+f"(c[1]), "+f"(c[2]), "+f"(c[3])
        : "r"(a[0]), "r"(a[1]), "r"(a[2]), "r"(a[3]), "r"(b[0]), "r"(b[1]));
}

// pack two fp32 into bf16x2 + residual bf16x2
__device__ __forceinline__ void split2(float v0, float v1,
                                       __nv_bfloat162& hi2, __nv_bfloat162& lo2) {
    __nv_bfloat16 h0 = __float2bfloat16(v0), h1 = __float2bfloat16(v1);
    hi2 = __nv_bfloat162(h0, h1);
    lo2 = __nv_bfloat162(__float2bfloat16(v0 - __bfloat162float(h0)),
                         __float2bfloat16(v1 - __bfloat162float(h1)));
}

// ---------------------------------------------------------------------------
// Tensor-core GEMM: C(128x128 tiles) = A * B^T, 3-MMA bf16 split precision.
// NTN = n-tiles (8 cols each) per warp:
//   NTN=4: 256 thr, 8 warps 2x4, warp 64x32  (epilogue-heavy / low-occupancy)
//   NTN=8: 128 thr, 4 warps 2x2, warp 64x64  (mainloop-bound, big grids)
// KSPLIT: blockIdx.z is a K-chunk index (Kdim/gridDim.z per chunk); fp32
//   partial tiles go to Cf + z*sC. A/B are NOT batch-advanced (pass sA=sB=0).
// EPI: 0 = fp32 out (+bias), 1 = bf16 hi/lo out, 3 = QKV-routed (Q/K direct,
//      V-slot transposed via smem staging). hi/lo stores are packed bf16x2.
// CAUSAL: exact triangular grid decode, longest-first
// ---------------------------------------------------------------------------
#define STAGE_BYTES 32768
#define OFF_AHI 0
#define OFF_ALO 8192
#define OFF_BHI 16384
#define OFF_BLO 24576
#define SMEM_BYTES 65536     // 2 stages
#define TPITCH 136           // transpose staging pitch (bf16 elements)

template<int EPI, bool CAUSAL, bool KBOUND, bool HASBIAS, bool REV, int NTN, bool KSPLIT = false>
__global__ void __launch_bounds__((NTN==4 ? 256 : 128), 2)
k_tc(const __nv_bfloat16* __restrict__ Ahi, const __nv_bfloat16* __restrict__ Alo,
     const __nv_bfloat16* __restrict__ Bhi, const __nv_bfloat16* __restrict__ Blo,
     float* __restrict__ Cf, __nv_bfloat16* __restrict__ Chi, __nv_bfloat16* __restrict__ Clo,
     const float* __restrict__ bias,
     int N, int Kdim, long long sA, long long sB, long long sC)
{
    constexpr int NT = (NTN==4 ? 256 : 128);   // threads
    constexpr int WNOFF = NTN * 8;             // warp n-span
    int m0, n0;
    if (CAUSAL) {
        // longest-first: reverse the triangular index
        const int tix = (int)gridDim.x - 1 - (int)blockIdx.x;
        int mb = (int)((sqrtf(8.f * tix + 1.f) - 1.f) * 0.5f + 1e-4f);
        while ((mb + 1) * (mb + 2) / 2 <= tix) ++mb;
        while (mb * (mb + 1) / 2 > tix) --mb;
        const int nb = tix - mb * (mb + 1) / 2;
        m0 = mb * 128;
        n0 = nb * 128;
    } else {
        const int by = REV ? (gridDim.y - 1 - blockIdx.y) : blockIdx.y;
        m0 = by * 128;
        n0 = blockIdx.x * 128;
    }
    const long long b = blockIdx.z;
    if (!KSPLIT) { Ahi += b * sA; Alo += b * sA; Bhi += b * sB; Blo += b * sB; }

    extern __shared__ char smem[];
    const uint32_t sb = smem_u32(smem);
    const int tid = threadIdx.x, lane = tid & 31, wid = tid >> 5;
    const int wm = wid & 1, wn = wid >> 1;     // warp tile 64(m) x WNOFF(n)

    int kstart = 0, kend;
    if (KSPLIT) {
        const int kch = Kdim / (int)gridDim.z;
        kstart = (int)b * kch;
        kend = kstart + kch;
    } else {
        kend = KBOUND ? (m0 + 128) : Kdim;
    }
    const int c0 = kstart >> 5;
    const int cN = kend >> 5;

    float acc[4][NTN][4];
    #pragma unroll
    for (int i = 0; i < 4; ++i)
        #pragma unroll
        for (int j = 0; j < NTN; ++j)
            #pragma unroll
            for (int r = 0; r < 4; ++r) acc[i][j][r] = 0.f;

    // stage loader: 4 tiles of 128 rows x 64B, SWZ64 layout, cp.async 16B
    auto load_stage = [&](int c, int s) {
        const int k0 = c << 5;
        const uint32_t sbase = sb + s * STAGE_BYTES;
        #pragma unroll
        for (int h = 0; h < 512/NT; ++h) {
            const int idx = tid + h * NT;      // 0..511
            const int row = idx >> 2, ch = idx & 3;
            const uint32_t so = SWZ64(row * 64 + ch * 16);
            const size_t gA = (size_t)(m0 + row) * Kdim + k0 + ch * 8;
            const size_t gB = (size_t)(n0 + row) * Kdim + k0 + ch * 8;
            CP16(sbase + OFF_AHI + so, Ahi + gA);
            CP16(sbase + OFF_ALO + so, Alo + gA);
            CP16(sbase + OFF_BHI + so, Bhi + gB);
            CP16(sbase + OFF_BLO + so, Blo + gB);
        }
    };

    load_stage(c0, c0 & 1); CPCOMMIT();

    // Single-barrier pipeline: wait(c) -> barrier -> issue(c+1) -> consume(c).
    for (int c = c0; c < cN; ++c) {
        CPWAIT(0);
        __syncthreads();
        if (c + 1 < cN) { load_stage(c + 1, (c + 1) & 1); CPCOMMIT(); }

        const uint32_t sA = sb + (c & 1) * STAGE_BYTES;
        #pragma unroll
        for (int kk = 0; kk < 32; kk += 16) {
            // B fragments: NTN nt tiles (hi+lo)
            uint32_t bhi[NTN][2], blo[NTN][2];
            const int brow  = (lane & 7) + ((lane & 16) ? 8 : 0);
            const int bkoff = (lane & 8) ? 8 : 0;
            #pragma unroll
            for (int np = 0; np < NTN/2; ++np) {
                const uint32_t off = SWZ64((wn*WNOFF + np*16 + brow) * 64 + (kk + bkoff) * 2);
                uint32_t t4[4];
                ldm4(t4, sA + OFF_BHI + off);
                bhi[np*2][0] = t4[0]; bhi[np*2][1] = t4[1];
                bhi[np*2+1][0] = t4[2]; bhi[np*2+1][1] = t4[3];
                ldm4(t4, sA + OFF_BLO + off);
                blo[np*2][0] = t4[0]; blo[np*2][1] = t4[1];
                blo[np*2+1][0] = t4[2]; blo[np*2+1][1] = t4[3];
            }
            // A fragments: 4 mt tiles, hi and lo in separate regs
            const int arow  = lane & 15;
            const int akoff = (lane >> 4) << 3;
            uint32_t ahi[4][4], alo[4][4];
            #pragma unroll
            for (int mt = 0; mt < 4; ++mt) {
                const uint32_t off = SWZ64((wm*64 + mt*16 + arow) * 64 + (kk + akoff) * 2);
                ldm4(ahi[mt], sA + OFF_AHI + off);
                ldm4(alo[mt], sA + OFF_ALO + off);
            }
            // pass 1: hi*hi
            #pragma unroll
            for (int mt = 0; mt < 4; ++mt)
                #pragma unroll
                for (int nt = 0; nt < NTN; ++nt)
                    mma16816(acc[mt][nt], ahi[mt], bhi[nt]);
            // pass 2: hi*lo
            #pragma unroll
            for (int mt = 0; mt < 4; ++mt)
                #pragma unroll
                for (int nt = 0; nt < NTN; ++nt)
                    mma16816(acc[mt][nt], ahi[mt], blo[nt]);
            // pass 3: lo*hi
            #pragma unroll
            for (int mt = 0; mt < 4; ++mt)
                #pragma unroll
                for (int nt = 0; nt < NTN; ++nt)
                    mma16816(acc[mt][nt], alo[mt], bhi[nt]);
        }
    }

    // Epilogue. C frag: (c0,c1) row g cols t*2,t*2+1; (c2,c3) row g+8.
    const int g = lane >> 2, t = lane & 3;
    const bool vpath = (EPI == 3) && (n0 >= 2*DIM);
    if (vpath) {
        // V-slot (x @ Wc^T): smem-staged transpose [n][m], coalesced stores.
        __syncthreads();   // laggards may still be reading stage smem
        __nv_bfloat16* tsm = (__nv_bfloat16*)smem;
        const int bb = m0 >> 11, sbase_s = m0 & 2047;
        const int nvl0 = n0 - 2*DIM;
        #pragma unroll
        for (int comp = 0; comp < 2; ++comp) {
            #pragma unroll
            for (int mt = 0; mt < 4; ++mt)
                #pragma unroll
                for (int nt = 0; nt < NTN; ++nt)
                    #pragma unroll
                    for (int h = 0; h < 2; ++h) {
                        const int ml = wm*64 + mt*16 + g + h*8;
                        const int nl = wn*WNOFF + nt*8 + t*2;
                        float v0 = acc[mt][nt][h*2], v1 = acc[mt][nt][h*2+1];
                        __nv_bfloat162 hi2, lo2;
                        split2(v0, v1, hi2, lo2);
                        __nv_bfloat162 o2 = (comp == 0) ? hi2 : lo2;
                        tsm[(size_t)nl * TPITCH + ml]     = o2.x;
                        tsm[(size_t)(nl+1) * TPITCH + ml] = o2.y;
                    }
            __syncthreads();
            __nv_bfloat16* dst = (comp == 0) ? g_Vthi : g_Vtlo;
            // NT threads cover 128 rows x (NT/128) col-chunks
            constexpr int CHW = 16384 / NT;    // bf16 per thread (64 or 128)
            const int nl = tid / (NT/128), mh = (tid % (NT/128)) * CHW;
            const __nv_bfloat16* srow = tsm + (size_t)nl * TPITCH + mh;
            __nv_bfloat16* drow = dst + ((size_t)bb * DIM + (nvl0 + nl)) * SEQ + sbase_s + mh;
            #pragma unroll
            for (int q = 0; q < CHW/8; ++q)
                *(uint4*)(drow + q*8) = *(const uint4*)(srow + q*8);
            __syncthreads();
        }
        return;
    }
    #pragma unroll
    for (int mt = 0; mt < 4; ++mt)
        #pragma unroll
        for (int nt = 0; nt < NTN; ++nt)
            #pragma unroll
            for (int h = 0; h < 2; ++h) {
                const int m  = m0 + wm*64 + mt*16 + g + h*8;
                const int nb = n0 + wn*WNOFF + nt*8 + t*2;
                float v0 = acc[mt][nt][h*2], v1 = acc[mt][nt][h*2+1];
                if (EPI == 0) {
                    if (HASBIAS) { v0 += bias[nb]; v1 += bias[nb+1]; }
                    float* o = Cf + b*sC + (size_t)m*N + nb;
                    o[0] = v0; o[1] = v1;
                } else if (EPI == 1) {
                    const size_t base = (size_t)(b*sC) + (size_t)m*N + nb;
                    __nv_bfloat162 hi2, lo2;
                    split2(v0, v1, hi2, lo2);
                    *(__nv_bfloat162*)(Chi + base) = hi2;
                    *(__nv_bfloat162*)(Clo + base) = lo2;
                } else {  // EPI==3, Q/K route
                    const int which = nb >> 10;         // 0=Q, 1=K
                    const int nl = nb & 1023;
                    __nv_bfloat16* dh = which ? g_Khi : g_Qhi;
                    __nv_bfloat16* dl = which ? g_Klo : g_Qlo;
                    const size_t base = (size_t)m * DIM + nl;
                    __nv_bfloat162 hi2, lo2;
                    split2(v0, v1, hi2, lo2);
                    *(__nv_bfloat162*)(dh + base) = hi2;
                    *(__nv_bfloat162*)(dl + base) = lo2;
                }
            }
}

// ---------------------------------------------------------------------------
// fp32 -> (bf16 hi, bf16 lo) split, grid-strided, 4 elements per thread
// ---------------------------------------------------------------------------
__global__ void __launch_bounds__(256)
k_split(const float* __restrict__ src, __nv_bfloat16* __restrict__ hi,
        __nv_bfloat16* __restrict__ lo, int n)
{
    for (int i = (blockIdx.x * 256 + threadIdx.x) * 4; i < n; i += gridDim.x * 1024) {
        float4 v = *(const float4*)(src + i);
        __nv_bfloat162 h2a, l2a, h2b, l2b;
        split2(v.x, v.y, h2a, l2a);
        split2(v.z, v.w, h2b, l2b);
        __nv_bfloat162* ph = (__nv_bfloat162*)(hi + i);
        ph[0] = h2a; ph[1] = h2b;
        __nv_bfloat162* pl = (__nv_bfloat162*)(lo + i);
        pl[0] = l2a; pl[1] = l2b;
    }
}

// One launch: split Wq -> W[0], Wk -> W[1], Wo -> Wo buf (3 x DIM*DIM).
__global__ void __launch_bounds__(256)
k_split_w(const float* __restrict__ sq, const float* __restrict__ sk,
          const float* __restrict__ so,
          __nv_bfloat16* __restrict__ Whi, __nv_bfloat16* __restrict__ Wlo,
          __nv_bfloat16* __restrict__ Wohi, __nv_bfloat16* __restrict__ Wolo)
{
    const int i = (blockIdx.x * 256 + threadIdx.x) * 4;   // over 3*DIM*DIM
    const int w = i >> 20;                                // DIM*DIM = 1<<20
    const int off = i & (DIM*DIM - 1);
    const float* src = (w == 0) ? sq : (w == 1) ? sk : so;
    __nv_bfloat16* dh = (w == 2) ? Wohi : (Whi + (size_t)w * DIM*DIM);
    __nv_bfloat16* dl = (w == 2) ? Wolo : (Wlo + (size_t)w * DIM*DIM);
    float4 v = *(const float4*)(src + off);
    __nv_bfloat162 h2a, l2a, h2b, l2b;
    split2(v.x, v.y, h2a, l2a);
    split2(v.z, v.w, h2b, l2b);
    __nv_bfloat162* ph = (__nv_bfloat162*)(dh + off);
    ph[0] = h2a; ph[1] = h2b;
    __nv_bfloat162* pl = (__nv_bfloat162*)(dl + off);
    pl[0] = l2a; pl[1] = l2b;
}

// Transpose-split: Wvt[j][k] = split(Wv[k][j]). 32x32 smem tiles.
__global__ void __launch_bounds__(256)
k_split_t(const float* __restrict__ src, __nv_bfloat16* __restrict__ hi,
          __nv_bfloat16* __restrict__ lo)
{
    __shared__ float tile[32][33];
    const int k0 = blockIdx.y * 32, j0 = blockIdx.x * 32;
    const int tx = threadIdx.x & 31, ty = threadIdx.x >> 5;   // 32 x 8
    #pragma unroll
    for (int i = 0; i < 4; ++i)
        tile[ty + i*8][tx] = src[(size_t)(k0 + ty + i*8) * DIM + j0 + tx];
    __syncthreads();
    #pragma unroll
    for (int i = 0; i < 4; ++i) {
        const int j = ty + i*8;
        float v = tile[tx][j];
        __nv_bfloat16 h = __float2bfloat16(v);
        const size_t o = (size_t)(j0 + j) * DIM + k0 + tx;
        hi[o] = h;
        lo[o] = __float2bfloat16(v - __bfloat162float(h));
    }
}

// Reduce 4 fp32 split-K partials of Wc and emit hi/lo split.
__global__ void __launch_bounds__(256)
k_wc_reduce(const float* __restrict__ part,
            __nv_bfloat16* __restrict__ hi, __nv_bfloat16* __restrict__ lo)
{
    const int i = (blockIdx.x * 256 + threadIdx.x) * 2;   // over DIM*DIM
    const size_t D2 = (size_t)DIM * DIM;
    float v0 = part[i]   + part[i + D2]   + part[i + 2*D2]   + part[i + 3*D2];
    float v1 = part[i+1] + part[i+1 + D2] + part[i+1 + 2*D2] + part[i+1 + 3*D2];
    __nv_bfloat162 h2, l2;
    split2(v0, v1, h2, l2);
    *(__nv_bfloat162*)(hi + i) = h2;
    *(__nv_bfloat162*)(lo + i) = l2;
}

// ---------------------------------------------------------------------------
// Causal row softmax, vectorized: float4 logit loads (row buffer is full S,
// masked beyond len), one exp pass, packed bf16x2 weight stores zero-padded
// to the next 128 boundary (PV K-bound). 256 threads, 4 contiguous elems x 2.
// ---------------------------------------------------------------------------
__global__ void __launch_bounds__(256)
k_softmax(const float* __restrict__ Pf, __nv_bfloat16* __restrict__ Phi,
          __nv_bfloat16* __restrict__ Plo, int S)
{
    const int b = blockIdx.z;
    const int row = blockIdx.x;
    const float* r = Pf + ((size_t)b * S + row) * S;
    __nv_bfloat16* oh = Phi + ((size_t)b * S + row) * S;
    __nv_bfloat16* ol = Plo + ((size_t)b * S + row) * S;
    const int len = row + 1;
    const int zend = ((row >> 7) + 1) << 7;   // next 128 boundary
    const int tid = threadIdx.x;

    __shared__ float red[8];

    float4 xv[2];
    float m = -INFINITY;
    #pragma unroll
    for (int j = 0; j < 2; ++j) {
        const int base = j * 1024 + tid * 4;
        xv[j] = *(const float4*)(r + base);   // always in-bounds (row len S)
        if (base + 0 < len) m = fmaxf(m, xv[j].x);
        if (base + 1 < len) m = fmaxf(m, xv[j].y);
        if (base + 2 < len) m = fmaxf(m, xv[j].z);
        if (base + 3 < len) m = fmaxf(m, xv[j].w);
    }
    #pragma unroll
    for (int o = 16; o; o >>= 1) m = fmaxf(m, __shfl_xor_sync(0xffffffffu, m, o));
    if ((tid & 31) == 0) red[tid >> 5] = m;
    __syncthreads();
    float mm = -INFINITY;
    #pragma unroll
    for (int i = 0; i < 8; ++i) mm = fmaxf(mm, red[i]);
    __syncthreads();

    float4 ev[2];
    float s = 0.f;
    #pragma unroll
    for (int j = 0; j < 2; ++j) {
        const int base = j * 1024 + tid * 4;
        ev[j].x = (base + 0 < len) ? __expf(xv[j].x - mm) : 0.f;
        ev[j].y = (base + 1 < len) ? __expf(xv[j].y - mm) : 0.f;
        ev[j].z = (base + 2 < len) ? __expf(xv[j].z - mm) : 0.f;
        ev[j].w = (base + 3 < len) ? __expf(xv[j].w - mm) : 0.f;
        s += ev[j].x + ev[j].y + ev[j].z + ev[j].w;
    }
    #pragma unroll
    for (int o = 16; o; o >>= 1) s += __shfl_xor_sync(0xffffffffu, s, o);
    if ((tid & 31) == 0) red[tid >> 5] = s;
    __syncthreads();
    float ss = 0.f;
    #pragma unroll
    for (int i = 0; i < 8; ++i) ss += red[i];
    const float inv = 1.f / ss;

    #pragma unroll
    for (int j = 0; j < 2; ++j) {
        const int base = j * 1024 + tid * 4;
        if (base >= zend) continue;
        float p0 = ev[j].x * inv, p1 = ev[j].y * inv;
        float p2 = ev[j].z * inv, p3 = ev[j].w * inv;
        __nv_bfloat162 h2a, l2a, h2b, l2b;
        split2(p0, p1, h2a, l2a);
        split2(p2, p3, h2b, l2b);
        __nv_bfloat162* ph = (__nv_bfloat162*)(oh + base);
        ph[0] = h2a; ph[1] = h2b;
        __nv_bfloat162* pl = (__nv_bfloat162*)(ol + base);
        pl[0] = l2a; pl[1] = l2b;
    }
}

// ---------------------------------------------------------------------------
extern "C" void kernel_launch(void* const* d_in, const int* in_sizes, int n_in,
                              void* d_out, int out_size)
{
    const float* x  = (const float*)d_in[0];
    const float* WQ = (const float*)d_in[1];
    const float* WK = (const float*)d_in[2];
    const float* WV = (const float*)d_in[3];
    const float* WO = (const float*)d_in[4];
    const float* bO = (const float*)d_in[5];
    float* out = (float*)d_out;

    __nv_bfloat16 *xhi, *xlo, *Whi, *Wlo, *Wohi, *Wolo, *Wvthi, *Wvtlo;
    __nv_bfloat16 *Qhi, *Qlo, *Khi, *Klo, *Vthi, *Vtlo, *Phi, *Plo;
    float* Pf;
    cudaGetSymbolAddress((void**)&xhi, g_xhi);     cudaGetSymbolAddress((void**)&xlo, g_xlo);
    cudaGetSymbolAddress((void**)&Whi, g_Whi);     cudaGetSymbolAddress((void**)&Wlo, g_Wlo);
    cudaGetSymbolAddress((void**)&Wohi, g_Wohi);   cudaGetSymbolAddress((void**)&Wolo, g_Wolo);
    cudaGetSymbolAddress((void**)&Wvthi, g_Wvthi); cudaGetSymbolAddress((void**)&Wvtlo, g_Wvtlo);
    cudaGetSymbolAddress((void**)&Qhi, g_Qhi);     cudaGetSymbolAddress((void**)&Qlo, g_Qlo);
    cudaGetSymbolAddress((void**)&Khi, g_Khi);     cudaGetSymbolAddress((void**)&Klo, g_Klo);
    cudaGetSymbolAddress((void**)&Vthi, g_Vthi);   cudaGetSymbolAddress((void**)&Vtlo, g_Vtlo);
    cudaGetSymbolAddress((void**)&Phi, g_Phi);     cudaGetSymbolAddress((void**)&Plo, g_Plo);
    cudaGetSymbolAddress((void**)&Pf, g_Pf);

    cudaFuncSetAttribute(k_tc<0,false,false,false,false,4,true>, cudaFuncAttributeMaxDynamicSharedMemorySize, SMEM_BYTES);
    cudaFuncSetAttribute(k_tc<3,false,false,false,false,4>, cudaFuncAttributeMaxDynamicSharedMemorySize, SMEM_BYTES);
    cudaFuncSetAttribute(k_tc<0,true ,false,false,false,8>, cudaFuncAttributeMaxDynamicSharedMemorySize, SMEM_BYTES);
    cudaFuncSetAttribute(k_tc<0,false,true ,true ,true ,8>, cudaFuncAttributeMaxDynamicSharedMemorySize, SMEM_BYTES);

    // 1. Splits: x; Wq/Wk/Wo; Wv transposed (for the Wc GEMM's B operand)
    k_split<<<(MROWS*DIM/4 + 255)/256, 256>>>(x, xhi, xlo, MROWS*DIM);
    k_split_w<<<(3*DIM*DIM/4 + 255)/256, 256>>>(WQ, WK, WO, Whi, Wlo, Wohi, Wolo);
    k_split_t<<<dim3(DIM/32, DIM/32), 256>>>(WV, Wvthi, Wvtlo);

    // 2. Wc = Wo @ Wv via split-K (4 chunks, 256 CTAs) -> fp32 partials in Pf,
    //    then reduce + hi/lo split into the stacked V slot.
    k_tc<0,false,false,false,false,4,true><<<dim3(DIM/128, DIM/128, 4), 256, SMEM_BYTES>>>(
        Wohi, Wolo, Wvthi, Wvtlo, Pf, nullptr, nullptr, nullptr,
        DIM, DIM, 0, 0, (long long)DIM*DIM);
    k_wc_reduce<<<(DIM*DIM/2 + 255)/256, 256>>>(
        Pf, Whi + 2*(size_t)DIM*DIM, Wlo + 2*(size_t)DIM*DIM);

    // 3. Merged QK+VW projection (config A): x @ [Wq; Wk; Wc]^T, routed epilogue
    //    (V slot produces VW = x@Wc^T, stored transposed [B, D, S])
    k_tc<3,false,false,false,false,4><<<dim3(3*DIM/128, MROWS/128, 1), 256, SMEM_BYTES>>>(
        xhi, xlo, Whi, Wlo, nullptr, nullptr, nullptr, nullptr,
        3*DIM, DIM, 0, 0, 0);

    // 4. Causal scores (config B), exact triangular grid, longest-first
    k_tc<0,true,false,false,false,8><<<dim3(136, 1, BATCH), 128, SMEM_BYTES>>>(
        Qhi, Qlo, Khi, Klo, Pf, nullptr, nullptr, nullptr,
        SEQ, DIM, (long long)SEQ*DIM, (long long)SEQ*DIM, (long long)SEQ*SEQ);

    // 5. Softmax (vectorized float4 loads, packed bf16x2 stores)
    k_softmax<<<dim3(SEQ, 1, BATCH), 256>>>(Pf, Phi, Plo, SEQ);

    // 6. Final: out = P @ VW + b  (config B, fp32+bias epilogue, K-bounded,
    //    longest blocks first) — output projection is folded into VW.
    k_tc<0,false,true,true,true,8><<<dim3(DIM/128, SEQ/128, BATCH), 128, SMEM_BYTES>>>(
        Phi, Plo, Vthi, Vtlo, out, nullptr, nullptr, bO,
        DIM, SEQ, (long long)SEQ*SEQ, (long long)DIM*SEQ, (long long)SEQ*DIM);
}